// round 1
// baseline (speedup 1.0000x reference)
#include <cuda_runtime.h>
#include <math.h>

// Problem constants
#define BB   2
#define SQ   2048
#define SKV  2048
#define DD   1024
#define HH   16
#define DH   64

// Scratch (no cudaMalloc allowed) — module-load-time device globals.
__device__ float g_q   [(size_t)BB * SQ  * DD];        // 16.8 MB
__device__ float g_kv  [(size_t)BB * SKV * 2 * DD];    // 33.6 MB
__device__ float g_attn[(size_t)BB * SQ  * DD];        // 16.8 MB

// ---------------------------------------------------------------------------
// Tiled SGEMM: C[M,N] = A[M,K] @ W[K,N] + bias[N]
// BM=BN=64, BK=16, 256 threads, 4x4 microtile per thread.
// ---------------------------------------------------------------------------
__global__ __launch_bounds__(256)
void gemm_bias_kernel(const float* __restrict__ A,
                      const float* __restrict__ W,
                      const float* __restrict__ bias,
                      float* __restrict__ C,
                      int M, int N, int K)
{
    const int BM = 64, BN = 64, BK = 16;
    __shared__ float As[BK][BM];      // transposed A tile
    __shared__ float Bs[BK][BN];

    int tid = threadIdx.x;
    int tx  = tid & 15;               // 0..15 -> N microtile
    int ty  = tid >> 4;               // 0..15 -> M microtile

    int bm = blockIdx.y * BM;
    int bn = blockIdx.x * BN;

    // A-tile load mapping: 64 rows x 4 float4/row = 256 float4
    int arow = tid >> 2;              // 0..63
    int ac4  = tid & 3;               // 0..3
    // B-tile load mapping: 16 rows x 16 float4/row = 256 float4
    int brow = tid >> 4;              // 0..15
    int bc4  = tid & 15;              // 0..15

    float acc[4][4];
#pragma unroll
    for (int i = 0; i < 4; i++)
#pragma unroll
        for (int j = 0; j < 4; j++) acc[i][j] = 0.0f;

    for (int kt = 0; kt < K; kt += BK) {
        // load A tile (transposed into As[k][m])
        float4 av = *(const float4*)(A + (size_t)(bm + arow) * K + kt + ac4 * 4);
        As[ac4 * 4 + 0][arow] = av.x;
        As[ac4 * 4 + 1][arow] = av.y;
        As[ac4 * 4 + 2][arow] = av.z;
        As[ac4 * 4 + 3][arow] = av.w;
        // load B tile
        *(float4*)&Bs[brow][bc4 * 4] =
            *(const float4*)(W + (size_t)(kt + brow) * N + bn + bc4 * 4);
        __syncthreads();

#pragma unroll
        for (int kk = 0; kk < BK; kk++) {
            float4 a4 = *(const float4*)&As[kk][ty * 4];
            float4 b4 = *(const float4*)&Bs[kk][tx * 4];
            float a[4] = {a4.x, a4.y, a4.z, a4.w};
            float b[4] = {b4.x, b4.y, b4.z, b4.w};
#pragma unroll
            for (int i = 0; i < 4; i++)
#pragma unroll
                for (int j = 0; j < 4; j++)
                    acc[i][j] = fmaf(a[i], b[j], acc[i][j]);
        }
        __syncthreads();
    }

    // epilogue with bias
#pragma unroll
    for (int i = 0; i < 4; i++) {
        int row = bm + ty * 4 + i;
        int col = bn + tx * 4;
        float4 bv = *(const float4*)(bias + col);
        float4 o;
        o.x = acc[i][0] + bv.x;
        o.y = acc[i][1] + bv.y;
        o.z = acc[i][2] + bv.z;
        o.w = acc[i][3] + bv.w;
        *(float4*)(C + (size_t)row * N + col) = o;
    }
}

// ---------------------------------------------------------------------------
// Flash attention (fp32): one query row per thread, online softmax.
// grid: (SQ/128, H, B), 128 threads.
// K/V tiles of 64 rows x 64 dh staged in smem; dot reads are warp-broadcast.
// ---------------------------------------------------------------------------
__global__ __launch_bounds__(128)
void flash_attn_kernel(const float* __restrict__ qb,
                       const float* __restrict__ kvb,
                       float* __restrict__ ob)
{
    __shared__ float Ks[64][64];
    __shared__ float Vs[64][64];

    int t  = threadIdx.x;
    int b  = blockIdx.z;
    int h  = blockIdx.y;
    int qi = blockIdx.x * 128 + t;

    const float* qp = qb + (size_t)(b * SQ + qi) * DD + h * DH;
    float q[DH];
#pragma unroll
    for (int i = 0; i < 16; i++) {
        float4 v = *(const float4*)(qp + i * 4);
        q[i * 4 + 0] = v.x; q[i * 4 + 1] = v.y;
        q[i * 4 + 2] = v.z; q[i * 4 + 3] = v.w;
    }

    float acc[DH];
#pragma unroll
    for (int d = 0; d < DH; d++) acc[d] = 0.0f;
    float m = -INFINITY;
    float l = 0.0f;

    const float scale = 0.125f;  // 1/sqrt(64)

    for (int kt = 0; kt < SKV / 64; kt++) {
        __syncthreads();
        // stage K/V tiles: 64 rows x 64 cols each = 1024 float4 per tile
        const float* kbase = kvb + (size_t)(b * SKV + kt * 64) * (2 * DD) + h * DH;
        const float* vbase = kbase + DD;
#pragma unroll
        for (int i = 0; i < 8; i++) {
            int f  = i * 128 + t;       // float4 index 0..1023
            int r  = f >> 4;            // row 0..63
            int c4 = f & 15;            // float4 col 0..15
            ((float4*)Ks)[f] = *(const float4*)(kbase + (size_t)r * (2 * DD) + c4 * 4);
            ((float4*)Vs)[f] = *(const float4*)(vbase + (size_t)r * (2 * DD) + c4 * 4);
        }
        __syncthreads();

        for (int j = 0; j < 64; j++) {
            // s = q . K[j]  (4 partial sums to break the dependency chain)
            const float4* kr = (const float4*)&Ks[j][0];
            float s0 = 0.f, s1 = 0.f, s2 = 0.f, s3 = 0.f;
#pragma unroll
            for (int d4 = 0; d4 < 16; d4++) {
                float4 k4 = kr[d4];
                s0 = fmaf(q[d4 * 4 + 0], k4.x, s0);
                s1 = fmaf(q[d4 * 4 + 1], k4.y, s1);
                s2 = fmaf(q[d4 * 4 + 2], k4.z, s2);
                s3 = fmaf(q[d4 * 4 + 3], k4.w, s3);
            }
            float s = ((s0 + s1) + (s2 + s3)) * scale;

            if (s > m) {
                float corr = __expf(m - s);   // exp(-inf)=0 on first hit
                l *= corr;
#pragma unroll
                for (int d = 0; d < DH; d++) acc[d] *= corr;
                m = s;
            }
            float p = __expf(s - m);
            l += p;

            const float4* vr = (const float4*)&Vs[j][0];
#pragma unroll
            for (int d4 = 0; d4 < 16; d4++) {
                float4 v4 = vr[d4];
                acc[d4 * 4 + 0] = fmaf(p, v4.x, acc[d4 * 4 + 0]);
                acc[d4 * 4 + 1] = fmaf(p, v4.y, acc[d4 * 4 + 1]);
                acc[d4 * 4 + 2] = fmaf(p, v4.z, acc[d4 * 4 + 2]);
                acc[d4 * 4 + 3] = fmaf(p, v4.w, acc[d4 * 4 + 3]);
            }
        }
    }

    float inv = 1.0f / l;
    float* op = ob + (size_t)(b * SQ + qi) * DD + h * DH;
#pragma unroll
    for (int d4 = 0; d4 < 16; d4++) {
        float4 o;
        o.x = acc[d4 * 4 + 0] * inv;
        o.y = acc[d4 * 4 + 1] * inv;
        o.z = acc[d4 * 4 + 2] * inv;
        o.w = acc[d4 * 4 + 3] * inv;
        *(float4*)(op + d4 * 4) = o;
    }
}

// ---------------------------------------------------------------------------
// kernel_launch — graph-capturable, allocation-free
// Inputs (metadata order): query_input, kv_input, Wq, bq, Wkv, bkv, Wo, bo
// ---------------------------------------------------------------------------
extern "C" void kernel_launch(void* const* d_in, const int* in_sizes, int n_in,
                              void* d_out, int out_size)
{
    (void)in_sizes; (void)n_in; (void)out_size;
    const float* query = (const float*)d_in[0];
    const float* kvin  = (const float*)d_in[1];
    const float* Wq    = (const float*)d_in[2];
    const float* bq    = (const float*)d_in[3];
    const float* Wkv   = (const float*)d_in[4];
    const float* bkv   = (const float*)d_in[5];
    const float* Wo    = (const float*)d_in[6];
    const float* bo    = (const float*)d_in[7];
    float* out = (float*)d_out;

    float *qbuf, *kvbuf, *attnbuf;
    cudaGetSymbolAddress((void**)&qbuf,    g_q);
    cudaGetSymbolAddress((void**)&kvbuf,   g_kv);
    cudaGetSymbolAddress((void**)&attnbuf, g_attn);

    const int M = BB * SQ;   // 4096

    // Q = query @ Wq + bq          [4096, 1024]
    gemm_bias_kernel<<<dim3(DD / 64, M / 64), 256>>>(query, Wq, bq, qbuf, M, DD, DD);
    // KV = kv @ Wkv + bkv          [4096, 2048]
    gemm_bias_kernel<<<dim3(2 * DD / 64, M / 64), 256>>>(kvin, Wkv, bkv, kvbuf, M, 2 * DD, DD);
    // attention
    flash_attn_kernel<<<dim3(SQ / 128, HH, BB), 128>>>(qbuf, kvbuf, attnbuf);
    // out = attn @ Wo + bo         [4096, 1024]
    gemm_bias_kernel<<<dim3(DD / 64, M / 64), 256>>>(attnbuf, Wo, bo, out, M, DD, DD);
}

// round 3
// speedup vs baseline: 1.3408x; 1.3408x over previous
#include <cuda_runtime.h>
#include <cuda_bf16.h>
#include <math.h>
#include <stdint.h>

// Problem constants
#define BB   2
#define SQ   2048
#define SKV  2048
#define DD   1024
#define HH   16
#define DH   64
#define MM   (BB*SQ)   // 4096

typedef unsigned short ushort_t;

// ---------------------------------------------------------------------------
// Scratch (no cudaMalloc allowed)
// ---------------------------------------------------------------------------
__device__ float    g_q   [(size_t)MM * DD];
__device__ float    g_kv  [(size_t)MM * 2 * DD];
__device__ float    g_attn[(size_t)MM * DD];
__device__ ushort_t g_ah  [(size_t)MM * DD];
__device__ ushort_t g_al  [(size_t)MM * DD];
__device__ ushort_t g_kh  [(size_t)MM * DD];
__device__ ushort_t g_kl  [(size_t)MM * DD];
__device__ ushort_t g_wqh [(size_t)DD * DD];
__device__ ushort_t g_wql [(size_t)DD * DD];
__device__ ushort_t g_wkvh[(size_t)2 * DD * DD];
__device__ ushort_t g_wkvl[(size_t)2 * DD * DD];
__device__ ushort_t g_woh [(size_t)DD * DD];
__device__ ushort_t g_wol [(size_t)DD * DD];

// ---------------------------------------------------------------------------
// Helpers
// ---------------------------------------------------------------------------
__device__ __forceinline__ uint32_t smem_u32(const void* p) {
    uint32_t a;
    asm("{ .reg .u64 t; cvta.to.shared.u64 t, %1; cvt.u32.u64 %0, t; }"
        : "=r"(a) : "l"(p));
    return a;
}
__device__ __forceinline__ ushort_t f2bf(float v) {
    __nv_bfloat16 b = __float2bfloat16(v);
    return *reinterpret_cast<ushort_t*>(&b);
}
__device__ __forceinline__ float bf2f(ushort_t s) {
    __nv_bfloat16 b;
    *reinterpret_cast<ushort_t*>(&b) = s;
    return __bfloat162float(b);
}
// SW64 swizzle for 64-byte rows (XOR bits[5:4] with bits[8:7])
__device__ __forceinline__ uint32_t swz64(uint32_t off) {
    return off ^ ((off >> 3) & 0x30);
}
__device__ __forceinline__ void ldsm4(uint32_t* r, uint32_t addr) {
    asm volatile("ldmatrix.sync.aligned.m8n8.x4.shared.b16 {%0,%1,%2,%3}, [%4];"
        : "=r"(r[0]), "=r"(r[1]), "=r"(r[2]), "=r"(r[3]) : "r"(addr));
}
__device__ __forceinline__ void mma_bf16(float* d, const uint32_t* a, const uint32_t* b) {
    asm volatile(
        "mma.sync.aligned.m16n8k16.row.col.f32.bf16.bf16.f32 "
        "{%0,%1,%2,%3}, {%4,%5,%6,%7}, {%8,%9}, {%0,%1,%2,%3};"
        : "+f"(d[0]), "+f"(d[1]), "+f"(d[2]), "+f"(d[3])
        : "r"(a[0]), "r"(a[1]), "r"(a[2]), "r"(a[3]), "r"(b[0]), "r"(b[1]));
}
__device__ __forceinline__ void cp16(uint32_t saddr, const void* g) {
    asm volatile("cp.async.cg.shared.global [%0], [%1], 16;" :: "r"(saddr), "l"(g));
}

// ---------------------------------------------------------------------------
// Conversion kernels
// ---------------------------------------------------------------------------
__global__ __launch_bounds__(256)
void conv_hilo(const float* __restrict__ in,
               ushort_t* __restrict__ hi, ushort_t* __restrict__ lo, int n4)
{
    int i = blockIdx.x * 256 + threadIdx.x;
    if (i >= n4) return;
    float4 x = ((const float4*)in)[i];
    float v[4] = {x.x, x.y, x.z, x.w};
    ushort4 h, l;
    ushort_t hh[4], ll[4];
#pragma unroll
    for (int j = 0; j < 4; j++) {
        hh[j] = f2bf(v[j]);
        ll[j] = f2bf(v[j] - bf2f(hh[j]));
    }
    h.x = hh[0]; h.y = hh[1]; h.z = hh[2]; h.w = hh[3];
    l.x = ll[0]; l.y = ll[1]; l.z = ll[2]; l.w = ll[3];
    ((ushort4*)hi)[i] = h;
    ((ushort4*)lo)[i] = l;
}

// W[K,N] -> Wt[N,K] hi/lo (transpose + split)
__global__ __launch_bounds__(256)
void conv_w_t(const float* __restrict__ W,
              ushort_t* __restrict__ Th, ushort_t* __restrict__ Tl,
              int K, int N)
{
    __shared__ float t[32][33];
    int kt = blockIdx.y * 32, nt = blockIdx.x * 32;
    int tx = threadIdx.x, ty = threadIdx.y;   // 32 x 8
#pragma unroll
    for (int i = 0; i < 4; i++) {
        int r = ty + i * 8;
        t[r][tx] = W[(size_t)(kt + r) * N + nt + tx];
    }
    __syncthreads();
#pragma unroll
    for (int i = 0; i < 4; i++) {
        int nr = ty + i * 8;
        float v = t[tx][nr];
        ushort_t h = f2bf(v);
        size_t o = (size_t)(nt + nr) * K + kt + tx;
        Th[o] = h;
        Tl[o] = f2bf(v - bf2f(h));
    }
}

// ---------------------------------------------------------------------------
// bf16x3 HMMA GEMM:  C[M,N] = A[M,1024] @ Bt[N,1024]^T + bias
// Block tile 128x128, BK=32, 8 warps (warp tile 32x64), cp.async double buffer.
// Components in smem per stage: Ah, Al, Bh, Bl each 128x32 bf16 (8KB, SW64).
// ---------------------------------------------------------------------------
#define KC       32
#define NSTG     (DD / KC)         // 32
#define COMP_SZ  8192
#define STAGE_SZ (4 * COMP_SZ)     // 32KB
#define GT_SMEM  (2 * STAGE_SZ)    // 64KB

__global__ __launch_bounds__(256, 1)
void gemm_tc(const ushort_t* __restrict__ Ah, const ushort_t* __restrict__ Al,
             const ushort_t* __restrict__ Bh, const ushort_t* __restrict__ Bl,
             const float* __restrict__ bias, float* __restrict__ C, int N)
{
    extern __shared__ char smem[];
    const uint32_t sbase = smem_u32(smem);
    const int tid  = threadIdx.x;
    const int lane = tid & 31;
    const int wid  = tid >> 5;
    const int wm   = wid >> 1;          // 0..3
    const int wn   = wid & 1;           // 0..1
    const int mrow = wm * 32;
    const int ncol = wn * 64;
    const int bm = blockIdx.y * 128;
    const int bn = blockIdx.x * 128;

    const ushort_t* srcs[4]  = {Ah, Al, Bh, Bl};
    const int       rbase[4] = {bm, bm, bn, bn};

    float acc[2][8][4];
#pragma unroll
    for (int i = 0; i < 2; i++)
#pragma unroll
        for (int j = 0; j < 8; j++)
#pragma unroll
            for (int k = 0; k < 4; k++) acc[i][j][k] = 0.0f;

    // per-thread load mapping: idx = i*256 + tid -> row = idx>>2, chunk = idx&3
    const int lr[2] = {(0 * 256 + tid) >> 2, (1 * 256 + tid) >> 2};
    const int lc[2] = {(0 * 256 + tid) & 3,  (1 * 256 + tid) & 3};

    auto load_stage = [&](int c, int buf) {
        int k0 = c * KC;
        uint32_t sb = sbase + buf * STAGE_SZ;
#pragma unroll
        for (int comp = 0; comp < 4; comp++) {
#pragma unroll
            for (int i = 0; i < 2; i++) {
                const ushort_t* g = srcs[comp]
                    + (size_t)(rbase[comp] + lr[i]) * DD + k0 + lc[i] * 8;
                cp16(sb + comp * COMP_SZ + swz64(lr[i] * 64 + lc[i] * 16), g);
            }
        }
        asm volatile("cp.async.commit_group;" ::: "memory");
    };

    load_stage(0, 0);

    for (int c = 0; c < NSTG; c++) {
        int buf = c & 1;
        if (c + 1 < NSTG) {
            load_stage(c + 1, buf ^ 1);
            asm volatile("cp.async.wait_group 1;" ::: "memory");
        } else {
            asm volatile("cp.async.wait_group 0;" ::: "memory");
        }
        __syncthreads();

        uint32_t sb = sbase + buf * STAGE_SZ;
#pragma unroll
        for (int ks = 0; ks < 2; ks++) {
            // A fragments: comp 0 = hi, 1 = lo; 2 m-frags each
            uint32_t aF[2][2][4];
#pragma unroll
            for (int comp = 0; comp < 2; comp++)
#pragma unroll
                for (int i = 0; i < 2; i++) {
                    uint32_t row = mrow + i * 16 + (lane & 15);
                    uint32_t kb  = ks * 32 + ((lane >> 4) << 4);
                    ldsm4(aF[comp][i], sb + comp * COMP_SZ + swz64(row * 64 + kb));
                }
            // B fragments: comp 0 = hi, 1 = lo; 8 n-frags x 2 halves
            uint32_t bF[2][8][2];
#pragma unroll
            for (int comp = 0; comp < 2; comp++)
#pragma unroll
                for (int g = 0; g < 2; g++)
#pragma unroll
                    for (int h = 0; h < 2; h++) {
                        uint32_t row = ncol + g * 32 + lane;
                        uint32_t kb  = ks * 32 + h * 16;
                        uint32_t t4[4];
                        ldsm4(t4, sb + (2 + comp) * COMP_SZ + swz64(row * 64 + kb));
                        bF[comp][g * 4 + 0][h] = t4[0];
                        bF[comp][g * 4 + 1][h] = t4[1];
                        bF[comp][g * 4 + 2][h] = t4[2];
                        bF[comp][g * 4 + 3][h] = t4[3];
                    }
#pragma unroll
            for (int i = 0; i < 2; i++)
#pragma unroll
                for (int j = 0; j < 8; j++) {
                    mma_bf16(acc[i][j], aF[0][i], bF[0][j]);   // Ah*Bh
                    mma_bf16(acc[i][j], aF[1][i], bF[0][j]);   // Al*Bh
                    mma_bf16(acc[i][j], aF[0][i], bF[1][j]);   // Ah*Bl
                }
        }
        __syncthreads();
    }

    // epilogue
#pragma unroll
    for (int i = 0; i < 2; i++) {
        int row0 = bm + mrow + i * 16 + (lane >> 2);
#pragma unroll
        for (int j = 0; j < 8; j++) {
            int col = bn + ncol + j * 8 + (lane & 3) * 2;
            float2 b2 = *(const float2*)(bias + col);
            float2 o0 = {acc[i][j][0] + b2.x, acc[i][j][1] + b2.y};
            float2 o1 = {acc[i][j][2] + b2.x, acc[i][j][3] + b2.y};
            *(float2*)(C + (size_t)row0 * N + col)       = o0;
            *(float2*)(C + (size_t)(row0 + 8) * N + col) = o1;
        }
    }
}

// ---------------------------------------------------------------------------
// Flash attention (fp32) — unchanged (proven correct)
// ---------------------------------------------------------------------------
__global__ __launch_bounds__(128)
void flash_attn_kernel(const float* __restrict__ qb,
                       const float* __restrict__ kvb,
                       float* __restrict__ ob)
{
    __shared__ float Ks[64][64];
    __shared__ float Vs[64][64];

    int t  = threadIdx.x;
    int b  = blockIdx.z;
    int h  = blockIdx.y;
    int qi = blockIdx.x * 128 + t;

    const float* qp = qb + (size_t)(b * SQ + qi) * DD + h * DH;
    float q[DH];
#pragma unroll
    for (int i = 0; i < 16; i++) {
        float4 v = *(const float4*)(qp + i * 4);
        q[i * 4 + 0] = v.x; q[i * 4 + 1] = v.y;
        q[i * 4 + 2] = v.z; q[i * 4 + 3] = v.w;
    }

    float acc[DH];
#pragma unroll
    for (int d = 0; d < DH; d++) acc[d] = 0.0f;
    float m = -INFINITY;
    float l = 0.0f;
    const float scale = 0.125f;

    for (int kt = 0; kt < SKV / 64; kt++) {
        __syncthreads();
        const float* kbase = kvb + (size_t)(b * SKV + kt * 64) * (2 * DD) + h * DH;
        const float* vbase = kbase + DD;
#pragma unroll
        for (int i = 0; i < 8; i++) {
            int f  = i * 128 + t;
            int r  = f >> 4;
            int c4 = f & 15;
            ((float4*)Ks)[f] = *(const float4*)(kbase + (size_t)r * (2 * DD) + c4 * 4);
            ((float4*)Vs)[f] = *(const float4*)(vbase + (size_t)r * (2 * DD) + c4 * 4);
        }
        __syncthreads();

        for (int j = 0; j < 64; j++) {
            const float4* kr = (const float4*)&Ks[j][0];
            float s0 = 0.f, s1 = 0.f, s2 = 0.f, s3 = 0.f;
#pragma unroll
            for (int d4 = 0; d4 < 16; d4++) {
                float4 k4 = kr[d4];
                s0 = fmaf(q[d4 * 4 + 0], k4.x, s0);
                s1 = fmaf(q[d4 * 4 + 1], k4.y, s1);
                s2 = fmaf(q[d4 * 4 + 2], k4.z, s2);
                s3 = fmaf(q[d4 * 4 + 3], k4.w, s3);
            }
            float s = ((s0 + s1) + (s2 + s3)) * scale;

            if (s > m) {
                float corr = __expf(m - s);
                l *= corr;
#pragma unroll
                for (int d = 0; d < DH; d++) acc[d] *= corr;
                m = s;
            }
            float p = __expf(s - m);
            l += p;

            const float4* vr = (const float4*)&Vs[j][0];
#pragma unroll
            for (int d4 = 0; d4 < 16; d4++) {
                float4 v4 = vr[d4];
                acc[d4 * 4 + 0] = fmaf(p, v4.x, acc[d4 * 4 + 0]);
                acc[d4 * 4 + 1] = fmaf(p, v4.y, acc[d4 * 4 + 1]);
                acc[d4 * 4 + 2] = fmaf(p, v4.z, acc[d4 * 4 + 2]);
                acc[d4 * 4 + 3] = fmaf(p, v4.w, acc[d4 * 4 + 3]);
            }
        }
    }

    float inv = 1.0f / l;
    float* op = ob + (size_t)(b * SQ + qi) * DD + h * DH;
#pragma unroll
    for (int d4 = 0; d4 < 16; d4++) {
        float4 o;
        o.x = acc[d4 * 4 + 0] * inv;
        o.y = acc[d4 * 4 + 1] * inv;
        o.z = acc[d4 * 4 + 2] * inv;
        o.w = acc[d4 * 4 + 3] * inv;
        *(float4*)(op + d4 * 4) = o;
    }
}

// ---------------------------------------------------------------------------
// kernel_launch — graph-capturable, allocation-free
// Inputs: query_input, kv_input, Wq, bq, Wkv, bkv, Wo, bo
// ---------------------------------------------------------------------------
extern "C" void kernel_launch(void* const* d_in, const int* in_sizes, int n_in,
                              void* d_out, int out_size)
{
    (void)in_sizes; (void)n_in; (void)out_size;
    const float* query = (const float*)d_in[0];
    const float* kvin  = (const float*)d_in[1];
    const float* Wq    = (const float*)d_in[2];
    const float* bq    = (const float*)d_in[3];
    const float* Wkv   = (const float*)d_in[4];
    const float* bkv   = (const float*)d_in[5];
    const float* Wo    = (const float*)d_in[6];
    const float* bo    = (const float*)d_in[7];
    float* out = (float*)d_out;

    float *qbuf, *kvbuf, *attnbuf;
    ushort_t *ah, *al, *kh, *kl, *wqh, *wql, *wkvh, *wkvl, *woh, *wol;
    cudaGetSymbolAddress((void**)&qbuf,    g_q);
    cudaGetSymbolAddress((void**)&kvbuf,   g_kv);
    cudaGetSymbolAddress((void**)&attnbuf, g_attn);
    cudaGetSymbolAddress((void**)&ah,   g_ah);
    cudaGetSymbolAddress((void**)&al,   g_al);
    cudaGetSymbolAddress((void**)&kh,   g_kh);
    cudaGetSymbolAddress((void**)&kl,   g_kl);
    cudaGetSymbolAddress((void**)&wqh,  g_wqh);
    cudaGetSymbolAddress((void**)&wql,  g_wql);
    cudaGetSymbolAddress((void**)&wkvh, g_wkvh);
    cudaGetSymbolAddress((void**)&wkvl, g_wkvl);
    cudaGetSymbolAddress((void**)&woh,  g_woh);
    cudaGetSymbolAddress((void**)&wol,  g_wol);

    cudaFuncSetAttribute(gemm_tc, cudaFuncAttributeMaxDynamicSharedMemorySize, GT_SMEM);

    const int n4 = MM * DD / 4;

    conv_hilo<<<(n4 + 255) / 256, 256>>>(query, ah, al, n4);
    conv_hilo<<<(n4 + 255) / 256, 256>>>(kvin, kh, kl, n4);
    conv_w_t<<<dim3(DD / 32, DD / 32), dim3(32, 8)>>>(Wq, wqh, wql, DD, DD);
    conv_w_t<<<dim3(2 * DD / 32, DD / 32), dim3(32, 8)>>>(Wkv, wkvh, wkvl, DD, 2 * DD);
    conv_w_t<<<dim3(DD / 32, DD / 32), dim3(32, 8)>>>(Wo, woh, wol, DD, DD);

    gemm_tc<<<dim3(DD / 128, MM / 128), 256, GT_SMEM>>>(ah, al, wqh, wql, bq, qbuf, DD);
    gemm_tc<<<dim3(2 * DD / 128, MM / 128), 256, GT_SMEM>>>(kh, kl, wkvh, wkvl, bkv, kvbuf, 2 * DD);

    flash_attn_kernel<<<dim3(SQ / 128, HH, BB), 128>>>(qbuf, kvbuf, attnbuf);

    conv_hilo<<<(n4 + 255) / 256, 256>>>(attnbuf, ah, al, n4);
    gemm_tc<<<dim3(DD / 128, MM / 128), 256, GT_SMEM>>>(ah, al, woh, wol, bo, out, DD);
}

// round 5
// speedup vs baseline: 3.3910x; 2.5291x over previous
#include <cuda_runtime.h>
#include <cuda_bf16.h>
#include <cuda_fp16.h>
#include <math.h>
#include <stdint.h>

// Problem constants
#define BB   2
#define SQ   2048
#define SKV  2048
#define DD   1024
#define HH   16
#define DH   64
#define MM   (BB*SQ)   // 4096

typedef unsigned short ushort_t;

// ---------------------------------------------------------------------------
// Scratch (no cudaMalloc allowed)
// ---------------------------------------------------------------------------
__device__ float    g_q   [(size_t)MM * DD];
__device__ float    g_kv  [(size_t)MM * 2 * DD];
__device__ float    g_attn[(size_t)MM * DD];
__device__ ushort_t g_ah  [(size_t)MM * DD];
__device__ ushort_t g_al  [(size_t)MM * DD];
__device__ ushort_t g_kh  [(size_t)MM * DD];
__device__ ushort_t g_kl  [(size_t)MM * DD];
__device__ ushort_t g_pkh [(size_t)MM * DD];   // projected K hi (bf16)
__device__ ushort_t g_pkl [(size_t)MM * DD];   // projected K lo (bf16)
__device__ ushort_t g_pvh [(size_t)MM * DD];   // projected V hi (fp16)
__device__ ushort_t g_pvl [(size_t)MM * DD];   // projected V lo (fp16)
__device__ ushort_t g_wqh [(size_t)DD * DD];
__device__ ushort_t g_wql [(size_t)DD * DD];
__device__ ushort_t g_wkvh[(size_t)2 * DD * DD];
__device__ ushort_t g_wkvl[(size_t)2 * DD * DD];
__device__ ushort_t g_woh [(size_t)DD * DD];
__device__ ushort_t g_wol [(size_t)DD * DD];

// ---------------------------------------------------------------------------
// Helpers
// ---------------------------------------------------------------------------
__device__ __forceinline__ uint32_t smem_u32(const void* p) {
    uint32_t a;
    asm("{ .reg .u64 t; cvta.to.shared.u64 t, %1; cvt.u32.u64 %0, t; }"
        : "=r"(a) : "l"(p));
    return a;
}
__device__ __forceinline__ ushort_t f2bf(float v) {
    __nv_bfloat16 b = __float2bfloat16(v);
    return *reinterpret_cast<ushort_t*>(&b);
}
__device__ __forceinline__ float bf2f(ushort_t s) {
    __nv_bfloat16 b;
    *reinterpret_cast<ushort_t*>(&b) = s;
    return __bfloat162float(b);
}
__device__ __forceinline__ ushort_t f2h(float v) {
    __half h = __float2half_rn(v);
    return *reinterpret_cast<ushort_t*>(&h);
}
__device__ __forceinline__ float h2f(ushort_t s) {
    __half h;
    *reinterpret_cast<ushort_t*>(&h) = s;
    return __half2float(h);
}
__device__ __forceinline__ uint32_t swz64(uint32_t off) {   // 64B rows
    return off ^ ((off >> 3) & 0x30);
}
__device__ __forceinline__ uint32_t swz128(uint32_t off) {  // 128B rows
    return off ^ ((off >> 3) & 0x70);
}
__device__ __forceinline__ void ldsm4(uint32_t* r, uint32_t addr) {
    asm volatile("ldmatrix.sync.aligned.m8n8.x4.shared.b16 {%0,%1,%2,%3}, [%4];"
        : "=r"(r[0]), "=r"(r[1]), "=r"(r[2]), "=r"(r[3]) : "r"(addr));
}
__device__ __forceinline__ void ldsm4t(uint32_t* r, uint32_t addr) {
    asm volatile("ldmatrix.sync.aligned.m8n8.x4.trans.shared.b16 {%0,%1,%2,%3}, [%4];"
        : "=r"(r[0]), "=r"(r[1]), "=r"(r[2]), "=r"(r[3]) : "r"(addr));
}
__device__ __forceinline__ void mma_bf16(float* d, const uint32_t* a, const uint32_t* b) {
    asm volatile(
        "mma.sync.aligned.m16n8k16.row.col.f32.bf16.bf16.f32 "
        "{%0,%1,%2,%3}, {%4,%5,%6,%7}, {%8,%9}, {%0,%1,%2,%3};"
        : "+f"(d[0]), "+f"(d[1]), "+f"(d[2]), "+f"(d[3])
        : "r"(a[0]), "r"(a[1]), "r"(a[2]), "r"(a[3]), "r"(b[0]), "r"(b[1]));
}
__device__ __forceinline__ void mma_f16(float* d, const uint32_t* a, const uint32_t* b) {
    asm volatile(
        "mma.sync.aligned.m16n8k16.row.col.f32.f16.f16.f32 "
        "{%0,%1,%2,%3}, {%4,%5,%6,%7}, {%8,%9}, {%0,%1,%2,%3};"
        : "+f"(d[0]), "+f"(d[1]), "+f"(d[2]), "+f"(d[3])
        : "r"(a[0]), "r"(a[1]), "r"(a[2]), "r"(a[3]), "r"(b[0]), "r"(b[1]));
}
__device__ __forceinline__ void cp16(uint32_t saddr, const void* g) {
    asm volatile("cp.async.cg.shared.global [%0], [%1], 16;" :: "r"(saddr), "l"(g));
}
__device__ __forceinline__ float ex2f(float x) {
    float y;
    asm("ex2.approx.ftz.f32 %0, %1;" : "=f"(y) : "f"(x));
    return y;
}
__device__ __forceinline__ uint32_t packh(float lo, float hi) {
    uint32_t r;
    asm("cvt.rn.f16x2.f32 %0, %1, %2;" : "=r"(r) : "f"(hi), "f"(lo));
    return r;
}

// ---------------------------------------------------------------------------
// Conversion kernels
// ---------------------------------------------------------------------------
__global__ __launch_bounds__(256)
void conv_hilo(const float* __restrict__ in,
               ushort_t* __restrict__ hi, ushort_t* __restrict__ lo, int n4)
{
    int i = blockIdx.x * 256 + threadIdx.x;
    if (i >= n4) return;
    float4 x = ((const float4*)in)[i];
    float v[4] = {x.x, x.y, x.z, x.w};
    ushort_t hh[4], ll[4];
#pragma unroll
    for (int j = 0; j < 4; j++) {
        hh[j] = f2bf(v[j]);
        ll[j] = f2bf(v[j] - bf2f(hh[j]));
    }
    ushort4 h = {hh[0], hh[1], hh[2], hh[3]};
    ushort4 l = {ll[0], ll[1], ll[2], ll[3]};
    ((ushort4*)hi)[i] = h;
    ((ushort4*)lo)[i] = l;
}

// kv [MM, 2DD]: K half -> (kh,kl) bf16 hi/lo, V half -> (vh,vl) fp16 hi/lo
__global__ __launch_bounds__(256)
void conv_kv(const float* __restrict__ kv,
             ushort_t* __restrict__ kh, ushort_t* __restrict__ kl,
             ushort_t* __restrict__ vh, ushort_t* __restrict__ vl, int n4)
{
    int i = blockIdx.x * 256 + threadIdx.x;     // over MM*DD/4
    if (i >= n4) return;
    int row = i / (DD / 4);
    int c4  = i % (DD / 4);
    const float4* krow = (const float4*)(kv + (size_t)row * 2 * DD);
    float4 xk = krow[c4];
    float4 xv = krow[DD / 4 + c4];
    float vk[4] = {xk.x, xk.y, xk.z, xk.w};
    float vv[4] = {xv.x, xv.y, xv.z, xv.w};
    ushort_t hh[4], ll[4], vhh[4], vll[4];
#pragma unroll
    for (int j = 0; j < 4; j++) {
        hh[j]  = f2bf(vk[j]);
        ll[j]  = f2bf(vk[j] - bf2f(hh[j]));
        vhh[j] = f2h(vv[j]);
        vll[j] = f2h(vv[j] - h2f(vhh[j]));
    }
    ushort4 h  = {hh[0], hh[1], hh[2], hh[3]};
    ushort4 l  = {ll[0], ll[1], ll[2], ll[3]};
    ushort4 vh4 = {vhh[0], vhh[1], vhh[2], vhh[3]};
    ushort4 vl4 = {vll[0], vll[1], vll[2], vll[3]};
    ((ushort4*)kh)[i] = h;
    ((ushort4*)kl)[i] = l;
    ((ushort4*)vh)[i] = vh4;
    ((ushort4*)vl)[i] = vl4;
}

// W[K,N] -> Wt[N,K] hi/lo (transpose + split)
__global__ __launch_bounds__(256)
void conv_w_t(const float* __restrict__ W,
              ushort_t* __restrict__ Th, ushort_t* __restrict__ Tl,
              int K, int N)
{
    __shared__ float t[32][33];
    int kt = blockIdx.y * 32, nt = blockIdx.x * 32;
    int tx = threadIdx.x, ty = threadIdx.y;   // 32 x 8
#pragma unroll
    for (int i = 0; i < 4; i++) {
        int r = ty + i * 8;
        t[r][tx] = W[(size_t)(kt + r) * N + nt + tx];
    }
    __syncthreads();
#pragma unroll
    for (int i = 0; i < 4; i++) {
        int nr = ty + i * 8;
        float v = t[tx][nr];
        ushort_t h = f2bf(v);
        size_t o = (size_t)(nt + nr) * K + kt + tx;
        Th[o] = h;
        Tl[o] = f2bf(v - bf2f(h));
    }
}

// ---------------------------------------------------------------------------
// bf16x3 HMMA GEMM (unchanged — proven at 1.1e-5)
// ---------------------------------------------------------------------------
#define KC       32
#define NSTG     (DD / KC)
#define COMP_SZ  8192
#define STAGE_SZ (4 * COMP_SZ)
#define GT_SMEM  (2 * STAGE_SZ)

__global__ __launch_bounds__(256, 1)
void gemm_tc(const ushort_t* __restrict__ Ah, const ushort_t* __restrict__ Al,
             const ushort_t* __restrict__ Bh, const ushort_t* __restrict__ Bl,
             const float* __restrict__ bias, float* __restrict__ C, int N)
{
    extern __shared__ char smem[];
    const uint32_t sbase = smem_u32(smem);
    const int tid  = threadIdx.x;
    const int lane = tid & 31;
    const int wid  = tid >> 5;
    const int wm   = wid >> 1;
    const int wn   = wid & 1;
    const int mrow = wm * 32;
    const int ncol = wn * 64;
    const int bm = blockIdx.y * 128;
    const int bn = blockIdx.x * 128;

    const ushort_t* srcs[4]  = {Ah, Al, Bh, Bl};
    const int       rbase[4] = {bm, bm, bn, bn};

    float acc[2][8][4];
#pragma unroll
    for (int i = 0; i < 2; i++)
#pragma unroll
        for (int j = 0; j < 8; j++)
#pragma unroll
            for (int k = 0; k < 4; k++) acc[i][j][k] = 0.0f;

    const int lr[2] = {(0 * 256 + tid) >> 2, (1 * 256 + tid) >> 2};
    const int lc[2] = {(0 * 256 + tid) & 3,  (1 * 256 + tid) & 3};

    auto load_stage = [&](int c, int buf) {
        int k0 = c * KC;
        uint32_t sb = sbase + buf * STAGE_SZ;
#pragma unroll
        for (int comp = 0; comp < 4; comp++) {
#pragma unroll
            for (int i = 0; i < 2; i++) {
                const ushort_t* g = srcs[comp]
                    + (size_t)(rbase[comp] + lr[i]) * DD + k0 + lc[i] * 8;
                cp16(sb + comp * COMP_SZ + swz64(lr[i] * 64 + lc[i] * 16), g);
            }
        }
        asm volatile("cp.async.commit_group;" ::: "memory");
    };

    load_stage(0, 0);

    for (int c = 0; c < NSTG; c++) {
        int buf = c & 1;
        if (c + 1 < NSTG) {
            load_stage(c + 1, buf ^ 1);
            asm volatile("cp.async.wait_group 1;" ::: "memory");
        } else {
            asm volatile("cp.async.wait_group 0;" ::: "memory");
        }
        __syncthreads();

        uint32_t sb = sbase + buf * STAGE_SZ;
#pragma unroll
        for (int ks = 0; ks < 2; ks++) {
            uint32_t aF[2][2][4];
#pragma unroll
            for (int comp = 0; comp < 2; comp++)
#pragma unroll
                for (int i = 0; i < 2; i++) {
                    uint32_t row = mrow + i * 16 + (lane & 15);
                    uint32_t kb  = ks * 32 + ((lane >> 4) << 4);
                    ldsm4(aF[comp][i], sb + comp * COMP_SZ + swz64(row * 64 + kb));
                }
            uint32_t bF[2][8][2];
#pragma unroll
            for (int comp = 0; comp < 2; comp++)
#pragma unroll
                for (int g = 0; g < 2; g++)
#pragma unroll
                    for (int h = 0; h < 2; h++) {
                        uint32_t row = ncol + g * 32 + lane;
                        uint32_t kb  = ks * 32 + h * 16;
                        uint32_t t4[4];
                        ldsm4(t4, sb + (2 + comp) * COMP_SZ + swz64(row * 64 + kb));
                        bF[comp][g * 4 + 0][h] = t4[0];
                        bF[comp][g * 4 + 1][h] = t4[1];
                        bF[comp][g * 4 + 2][h] = t4[2];
                        bF[comp][g * 4 + 3][h] = t4[3];
                    }
#pragma unroll
            for (int i = 0; i < 2; i++)
#pragma unroll
                for (int j = 0; j < 8; j++) {
                    mma_bf16(acc[i][j], aF[0][i], bF[0][j]);
                    mma_bf16(acc[i][j], aF[1][i], bF[0][j]);
                    mma_bf16(acc[i][j], aF[0][i], bF[1][j]);
                }
        }
        __syncthreads();
    }

#pragma unroll
    for (int i = 0; i < 2; i++) {
        int row0 = bm + mrow + i * 16 + (lane >> 2);
#pragma unroll
        for (int j = 0; j < 8; j++) {
            int col = bn + ncol + j * 8 + (lane & 3) * 2;
            float2 b2 = *(const float2*)(bias + col);
            float2 o0 = {acc[i][j][0] + b2.x, acc[i][j][1] + b2.y};
            float2 o1 = {acc[i][j][2] + b2.x, acc[i][j][3] + b2.y};
            *(float2*)(C + (size_t)row0 * N + col)       = o0;
            *(float2*)(C + (size_t)(row0 + 8) * N + col) = o1;
        }
    }
}

// ---------------------------------------------------------------------------
// Tensor-core flash attention.
// QK^T: bf16 3 passes. Softmax fp32. PV: fp16 P x fp16 V hi/lo (2 passes).
// ---------------------------------------------------------------------------
#define AT_KOFF_H 0
#define AT_KOFF_L 8192
#define AT_VOFF_H 16384
#define AT_VOFF_L 24576
#define AT_STAGE  32768
#define AT_SMEM   (2 * AT_STAGE)   // 64KB

__global__ __launch_bounds__(256, 1)
void flash_attn_tc(const ushort_t* __restrict__ qh, const ushort_t* __restrict__ ql,
                   const ushort_t* __restrict__ kh, const ushort_t* __restrict__ kl,
                   const ushort_t* __restrict__ vh, const ushort_t* __restrict__ vl,
                   float* __restrict__ ob)
{
    extern __shared__ char smem[];
    const uint32_t sb = smem_u32(smem);
    const int tid  = threadIdx.x;
    const int lane = tid & 31;
    const int w    = tid >> 5;
    const int b    = blockIdx.z;
    const int h    = blockIdx.y;
    const int q0   = blockIdx.x * 128;

    // ---- stage Q (hi, lo), extract A-fragments ----
    {
        const size_t qbase = (size_t)(b * SQ + q0) * DD + h * DH;
#pragma unroll
        for (int i = 0; i < 4; i++) {
            int vi = i * 256 + tid;           // 0..1023
            int r = vi >> 3, c = vi & 7;
            uint32_t so = swz128(r * 128 + c * 16);
            cp16(sb + so,         qh + qbase + (size_t)r * DD + c * 8);
            cp16(sb + 16384 + so, ql + qbase + (size_t)r * DD + c * 8);
        }
        asm volatile("cp.async.commit_group;" ::: "memory");
        asm volatile("cp.async.wait_group 0;" ::: "memory");
        __syncthreads();
    }
    uint32_t qf[2][4][4];
#pragma unroll
    for (int comp = 0; comp < 2; comp++)
#pragma unroll
        for (int t = 0; t < 4; t++) {
            uint32_t row = w * 16 + (lane & 15);
            uint32_t kb  = t * 32 + ((lane >> 4) << 4);
            ldsm4(qf[comp][t], sb + comp * 16384 + swz128(row * 128 + kb));
        }
    __syncthreads();

    // ---- state ----
    float of[8][4];
#pragma unroll
    for (int j = 0; j < 8; j++)
#pragma unroll
        for (int k = 0; k < 4; k++) of[j][k] = 0.0f;
    float m0 = -INFINITY, m1 = -INFINITY, l0 = 0.0f, l1 = 0.0f;

    const float SC  = 0.125f;
    const float L2E = 1.4426950408889634f;
    const float C2  = SC * L2E;

    const size_t kbase0 = (size_t)(b * SKV) * DD + h * DH;

    auto load_kv = [&](int tile, int buf) {
        uint32_t s = sb + buf * AT_STAGE;
        size_t gbase = kbase0 + (size_t)(tile * 64) * DD;
#pragma unroll
        for (int i = 0; i < 2; i++) {
            int vi = i * 256 + tid;           // 0..511
            int r = vi >> 3, c = vi & 7;
            uint32_t so = swz128(r * 128 + c * 16);
            size_t go = gbase + (size_t)r * DD + c * 8;
            cp16(s + AT_KOFF_H + so, kh + go);
            cp16(s + AT_KOFF_L + so, kl + go);
            cp16(s + AT_VOFF_H + so, vh + go);
            cp16(s + AT_VOFF_L + so, vl + go);
        }
        asm volatile("cp.async.commit_group;" ::: "memory");
    };

    load_kv(0, 0);

    for (int tile = 0; tile < SKV / 64; tile++) {
        int buf = tile & 1;
        if (tile + 1 < SKV / 64) {
            load_kv(tile + 1, buf ^ 1);
            asm volatile("cp.async.wait_group 1;" ::: "memory");
        } else {
            asm volatile("cp.async.wait_group 0;" ::: "memory");
        }
        __syncthreads();

        uint32_t s = sb + buf * AT_STAGE;

        // ---- S = Q @ K^T (bf16, 3 passes) ----
        float sf[8][4];
#pragma unroll
        for (int j = 0; j < 8; j++)
#pragma unroll
            for (int k = 0; k < 4; k++) sf[j][k] = 0.0f;

#pragma unroll
        for (int t = 0; t < 4; t++) {
            uint32_t bh[8][2];
#pragma unroll
            for (int g = 0; g < 2; g++)
#pragma unroll
                for (int hb = 0; hb < 2; hb++) {
                    uint32_t t4[4];
                    ldsm4(t4, s + AT_KOFF_H +
                          swz128((g * 32 + lane) * 128 + t * 32 + hb * 16));
                    bh[g * 4 + 0][hb] = t4[0];
                    bh[g * 4 + 1][hb] = t4[1];
                    bh[g * 4 + 2][hb] = t4[2];
                    bh[g * 4 + 3][hb] = t4[3];
                }
#pragma unroll
            for (int j = 0; j < 8; j++) mma_bf16(sf[j], qf[0][t], bh[j]);
#pragma unroll
            for (int j = 0; j < 8; j++) mma_bf16(sf[j], qf[1][t], bh[j]);

            uint32_t bl[8][2];
#pragma unroll
            for (int g = 0; g < 2; g++)
#pragma unroll
                for (int hb = 0; hb < 2; hb++) {
                    uint32_t t4[4];
                    ldsm4(t4, s + AT_KOFF_L +
                          swz128((g * 32 + lane) * 128 + t * 32 + hb * 16));
                    bl[g * 4 + 0][hb] = t4[0];
                    bl[g * 4 + 1][hb] = t4[1];
                    bl[g * 4 + 2][hb] = t4[2];
                    bl[g * 4 + 3][hb] = t4[3];
                }
#pragma unroll
            for (int j = 0; j < 8; j++) mma_bf16(sf[j], qf[0][t], bl[j]);
        }

        // ---- online softmax (fp32) ----
        float tm0 = -INFINITY, tm1 = -INFINITY;
#pragma unroll
        for (int j = 0; j < 8; j++) {
            tm0 = fmaxf(tm0, fmaxf(sf[j][0], sf[j][1]));
            tm1 = fmaxf(tm1, fmaxf(sf[j][2], sf[j][3]));
        }
        tm0 = fmaxf(tm0, __shfl_xor_sync(0xffffffffu, tm0, 1));
        tm0 = fmaxf(tm0, __shfl_xor_sync(0xffffffffu, tm0, 2));
        tm1 = fmaxf(tm1, __shfl_xor_sync(0xffffffffu, tm1, 1));
        tm1 = fmaxf(tm1, __shfl_xor_sync(0xffffffffu, tm1, 2));

        float mn0 = fmaxf(m0, tm0 * SC);
        float mn1 = fmaxf(m1, tm1 * SC);
        float a0 = ex2f((m0 - mn0) * L2E);
        float a1 = ex2f((m1 - mn1) * L2E);
        m0 = mn0; m1 = mn1;
        float base0 = mn0 * L2E, base1 = mn1 * L2E;

        float sum0 = 0.0f, sum1 = 0.0f;
#pragma unroll
        for (int j = 0; j < 8; j++) {
            sf[j][0] = ex2f(fmaf(sf[j][0], C2, -base0));
            sf[j][1] = ex2f(fmaf(sf[j][1], C2, -base0));
            sf[j][2] = ex2f(fmaf(sf[j][2], C2, -base1));
            sf[j][3] = ex2f(fmaf(sf[j][3], C2, -base1));
            sum0 += sf[j][0] + sf[j][1];
            sum1 += sf[j][2] + sf[j][3];
        }
        sum0 += __shfl_xor_sync(0xffffffffu, sum0, 1);
        sum0 += __shfl_xor_sync(0xffffffffu, sum0, 2);
        sum1 += __shfl_xor_sync(0xffffffffu, sum1, 1);
        sum1 += __shfl_xor_sync(0xffffffffu, sum1, 2);
        l0 = l0 * a0 + sum0;
        l1 = l1 * a1 + sum1;
#pragma unroll
        for (int j = 0; j < 8; j++) {
            of[j][0] *= a0; of[j][1] *= a0;
            of[j][2] *= a1; of[j][3] *= a1;
        }

        // ---- pack P into fp16 A fragments ----
        uint32_t pf[4][4];
#pragma unroll
        for (int t = 0; t < 4; t++) {
            pf[t][0] = packh(sf[2 * t][0],     sf[2 * t][1]);
            pf[t][1] = packh(sf[2 * t][2],     sf[2 * t][3]);
            pf[t][2] = packh(sf[2 * t + 1][0], sf[2 * t + 1][1]);
            pf[t][3] = packh(sf[2 * t + 1][2], sf[2 * t + 1][3]);
        }

        // ---- O += P @ (Vh + Vl), fp16 ----
#pragma unroll
        for (int t = 0; t < 4; t++) {
#pragma unroll
            for (int g = 0; g < 4; g++) {
                uint32_t row = t * 16 + (lane & 15);
                uint32_t nb  = g * 16 + ((lane >> 4) << 3);   // elems
                uint32_t soff = swz128(row * 128 + nb * 2);
                uint32_t t4[4];
                ldsm4t(t4, s + AT_VOFF_H + soff);
                mma_f16(of[g * 2],     pf[t], t4);
                mma_f16(of[g * 2 + 1], pf[t], t4 + 2);
                ldsm4t(t4, s + AT_VOFF_L + soff);
                mma_f16(of[g * 2],     pf[t], t4);
                mma_f16(of[g * 2 + 1], pf[t], t4 + 2);
            }
        }
        __syncthreads();
    }

    // ---- epilogue ----
    float inv0 = 1.0f / l0, inv1 = 1.0f / l1;
    int gr0 = q0 + w * 16 + (lane >> 2);
    int gr1 = gr0 + 8;
#pragma unroll
    for (int j = 0; j < 8; j++) {
        int col = h * DH + j * 8 + (lane & 3) * 2;
        float2 o0 = {of[j][0] * inv0, of[j][1] * inv0};
        float2 o1 = {of[j][2] * inv1, of[j][3] * inv1};
        *(float2*)(ob + (size_t)(b * SQ + gr0) * DD + col) = o0;
        *(float2*)(ob + (size_t)(b * SQ + gr1) * DD + col) = o1;
    }
}

// ---------------------------------------------------------------------------
// kernel_launch — graph-capturable, allocation-free
// Inputs: query_input, kv_input, Wq, bq, Wkv, bkv, Wo, bo
// ---------------------------------------------------------------------------
extern "C" void kernel_launch(void* const* d_in, const int* in_sizes, int n_in,
                              void* d_out, int out_size)
{
    (void)in_sizes; (void)n_in; (void)out_size;
    const float* query = (const float*)d_in[0];
    const float* kvin  = (const float*)d_in[1];
    const float* Wq    = (const float*)d_in[2];
    const float* bq    = (const float*)d_in[3];
    const float* Wkv   = (const float*)d_in[4];
    const float* bkv   = (const float*)d_in[5];
    const float* Wo    = (const float*)d_in[6];
    const float* bo    = (const float*)d_in[7];
    float* out = (float*)d_out;

    float *qbuf, *kvbuf, *attnbuf;
    ushort_t *ah, *al, *kh, *kl, *pkh, *pkl, *pvh, *pvl;
    ushort_t *wqh, *wql, *wkvh, *wkvl, *woh, *wol;
    cudaGetSymbolAddress((void**)&qbuf,    g_q);
    cudaGetSymbolAddress((void**)&kvbuf,   g_kv);
    cudaGetSymbolAddress((void**)&attnbuf, g_attn);
    cudaGetSymbolAddress((void**)&ah,   g_ah);
    cudaGetSymbolAddress((void**)&al,   g_al);
    cudaGetSymbolAddress((void**)&kh,   g_kh);
    cudaGetSymbolAddress((void**)&kl,   g_kl);
    cudaGetSymbolAddress((void**)&pkh,  g_pkh);
    cudaGetSymbolAddress((void**)&pkl,  g_pkl);
    cudaGetSymbolAddress((void**)&pvh,  g_pvh);
    cudaGetSymbolAddress((void**)&pvl,  g_pvl);
    cudaGetSymbolAddress((void**)&wqh,  g_wqh);
    cudaGetSymbolAddress((void**)&wql,  g_wql);
    cudaGetSymbolAddress((void**)&wkvh, g_wkvh);
    cudaGetSymbolAddress((void**)&wkvl, g_wkvl);
    cudaGetSymbolAddress((void**)&woh,  g_woh);
    cudaGetSymbolAddress((void**)&wol,  g_wol);

    cudaFuncSetAttribute(gemm_tc, cudaFuncAttributeMaxDynamicSharedMemorySize, GT_SMEM);
    cudaFuncSetAttribute(flash_attn_tc, cudaFuncAttributeMaxDynamicSharedMemorySize, AT_SMEM);

    const int n4 = MM * DD / 4;

    // Input/weight conversions
    conv_hilo<<<(n4 + 255) / 256, 256>>>(query, ah, al, n4);
    conv_hilo<<<(n4 + 255) / 256, 256>>>(kvin, kh, kl, n4);
    conv_w_t<<<dim3(DD / 32, DD / 32), dim3(32, 8)>>>(Wq, wqh, wql, DD, DD);
    conv_w_t<<<dim3(2 * DD / 32, DD / 32), dim3(32, 8)>>>(Wkv, wkvh, wkvl, DD, 2 * DD);
    conv_w_t<<<dim3(DD / 32, DD / 32), dim3(32, 8)>>>(Wo, woh, wol, DD, DD);

    // Projections
    gemm_tc<<<dim3(DD / 128, MM / 128), 256, GT_SMEM>>>(ah, al, wqh, wql, bq, qbuf, DD);
    gemm_tc<<<dim3(2 * DD / 128, MM / 128), 256, GT_SMEM>>>(kh, kl, wkvh, wkvl, bkv, kvbuf, 2 * DD);

    // Attention operand conversion (reuse ah/al for projected Q hi/lo)
    conv_hilo<<<(n4 + 255) / 256, 256>>>(qbuf, ah, al, n4);
    conv_kv<<<(n4 + 255) / 256, 256>>>(kvbuf, pkh, pkl, pvh, pvl, n4);

    // Tensor-core attention
    flash_attn_tc<<<dim3(SQ / 128, HH, BB), 256, AT_SMEM>>>(ah, al, pkh, pkl, pvh, pvl, attnbuf);

    // Output projection
    conv_hilo<<<(n4 + 255) / 256, 256>>>(attnbuf, ah, al, n4);
    gemm_tc<<<dim3(DD / 128, MM / 128), 256, GT_SMEM>>>(ah, al, woh, wol, bo, out, DD);
}

// round 6
// speedup vs baseline: 6.2048x; 1.8298x over previous
#include <cuda_runtime.h>
#include <cuda_bf16.h>
#include <cuda_fp16.h>
#include <math.h>
#include <stdint.h>

// Problem constants
#define BB   2
#define SQ   2048
#define SKV  2048
#define DD   1024
#define HH   16
#define DH   64
#define MM   (BB*SQ)   // 4096

typedef unsigned short ushort_t;

// ---------------------------------------------------------------------------
// Scratch (no cudaMalloc allowed)
// ---------------------------------------------------------------------------
__device__ float    g_q   [(size_t)MM * DD];
__device__ float    g_kv  [(size_t)MM * 2 * DD];
__device__ float    g_attn[(size_t)MM * DD];
__device__ ushort_t g_ah  [(size_t)MM * DD];       // activations fp16 (hi)
__device__ ushort_t g_al  [(size_t)MM * DD];       // activations fp16 (lo, O-proj only)
__device__ ushort_t g_kh  [(size_t)MM * DD];       // kv_input fp16
__device__ ushort_t g_pk  [(size_t)MM * DD];       // projected K fp16
__device__ ushort_t g_pv  [(size_t)MM * DD];       // projected V fp16
__device__ ushort_t g_wq  [(size_t)DD * DD];       // Wq^T fp16
__device__ ushort_t g_wkv [(size_t)2 * DD * DD];   // Wkv^T fp16
__device__ ushort_t g_woh [(size_t)DD * DD];       // Wo^T fp16 hi
__device__ ushort_t g_wol [(size_t)DD * DD];       // Wo^T fp16 lo

// ---------------------------------------------------------------------------
// Helpers
// ---------------------------------------------------------------------------
__device__ __forceinline__ uint32_t smem_u32(const void* p) {
    uint32_t a;
    asm("{ .reg .u64 t; cvta.to.shared.u64 t, %1; cvt.u32.u64 %0, t; }"
        : "=r"(a) : "l"(p));
    return a;
}
__device__ __forceinline__ ushort_t f2h(float v) {
    __half h = __float2half_rn(v);
    return *reinterpret_cast<ushort_t*>(&h);
}
__device__ __forceinline__ float h2f(ushort_t s) {
    __half h;
    *reinterpret_cast<ushort_t*>(&h) = s;
    return __half2float(h);
}
__device__ __forceinline__ uint32_t swz64(uint32_t off) {   // 64B rows
    return off ^ ((off >> 3) & 0x30);
}
__device__ __forceinline__ uint32_t swz128(uint32_t off) {  // 128B rows
    return off ^ ((off >> 3) & 0x70);
}
__device__ __forceinline__ void ldsm4(uint32_t* r, uint32_t addr) {
    asm volatile("ldmatrix.sync.aligned.m8n8.x4.shared.b16 {%0,%1,%2,%3}, [%4];"
        : "=r"(r[0]), "=r"(r[1]), "=r"(r[2]), "=r"(r[3]) : "r"(addr));
}
__device__ __forceinline__ void ldsm4t(uint32_t* r, uint32_t addr) {
    asm volatile("ldmatrix.sync.aligned.m8n8.x4.trans.shared.b16 {%0,%1,%2,%3}, [%4];"
        : "=r"(r[0]), "=r"(r[1]), "=r"(r[2]), "=r"(r[3]) : "r"(addr));
}
__device__ __forceinline__ void mma_f16(float* d, const uint32_t* a, const uint32_t* b) {
    asm volatile(
        "mma.sync.aligned.m16n8k16.row.col.f32.f16.f16.f32 "
        "{%0,%1,%2,%3}, {%4,%5,%6,%7}, {%8,%9}, {%0,%1,%2,%3};"
        : "+f"(d[0]), "+f"(d[1]), "+f"(d[2]), "+f"(d[3])
        : "r"(a[0]), "r"(a[1]), "r"(a[2]), "r"(a[3]), "r"(b[0]), "r"(b[1]));
}
__device__ __forceinline__ void cp16(uint32_t saddr, const void* g) {
    asm volatile("cp.async.cg.shared.global [%0], [%1], 16;" :: "r"(saddr), "l"(g));
}
__device__ __forceinline__ float ex2f(float x) {
    float y;
    asm("ex2.approx.ftz.f32 %0, %1;" : "=f"(y) : "f"(x));
    return y;
}
__device__ __forceinline__ uint32_t packh(float lo, float hi) {
    uint32_t r;
    asm("cvt.rn.f16x2.f32 %0, %1, %2;" : "=r"(r) : "f"(hi), "f"(lo));
    return r;
}

// ---------------------------------------------------------------------------
// Conversion kernels
// ---------------------------------------------------------------------------
__global__ __launch_bounds__(256)
void conv_h(const float* __restrict__ in, ushort_t* __restrict__ out, int n4)
{
    int i = blockIdx.x * 256 + threadIdx.x;
    if (i >= n4) return;
    float4 x = ((const float4*)in)[i];
    ushort4 o = {f2h(x.x), f2h(x.y), f2h(x.z), f2h(x.w)};
    ((ushort4*)out)[i] = o;
}

__global__ __launch_bounds__(256)
void conv_hilo_h(const float* __restrict__ in,
                 ushort_t* __restrict__ hi, ushort_t* __restrict__ lo, int n4)
{
    int i = blockIdx.x * 256 + threadIdx.x;
    if (i >= n4) return;
    float4 x = ((const float4*)in)[i];
    float v[4] = {x.x, x.y, x.z, x.w};
    ushort_t hh[4], ll[4];
#pragma unroll
    for (int j = 0; j < 4; j++) {
        hh[j] = f2h(v[j]);
        ll[j] = f2h(v[j] - h2f(hh[j]));
    }
    ushort4 h = {hh[0], hh[1], hh[2], hh[3]};
    ushort4 l = {ll[0], ll[1], ll[2], ll[3]};
    ((ushort4*)hi)[i] = h;
    ((ushort4*)lo)[i] = l;
}

// kv [MM, 2DD]: K half -> pk fp16, V half -> pv fp16
__global__ __launch_bounds__(256)
void conv_kv_h(const float* __restrict__ kv,
               ushort_t* __restrict__ pk, ushort_t* __restrict__ pv, int n4)
{
    int i = blockIdx.x * 256 + threadIdx.x;     // over MM*DD/4
    if (i >= n4) return;
    int row = i / (DD / 4);
    int c4  = i % (DD / 4);
    const float4* krow = (const float4*)(kv + (size_t)row * 2 * DD);
    float4 xk = krow[c4];
    float4 xv = krow[DD / 4 + c4];
    ushort4 k4 = {f2h(xk.x), f2h(xk.y), f2h(xk.z), f2h(xk.w)};
    ushort4 v4 = {f2h(xv.x), f2h(xv.y), f2h(xv.z), f2h(xv.w)};
    ((ushort4*)pk)[i] = k4;
    ((ushort4*)pv)[i] = v4;
}

// W[K,N] -> Wt[N,K] fp16 single
__global__ __launch_bounds__(256)
void conv_w_t_h(const float* __restrict__ W, ushort_t* __restrict__ T,
                int K, int N)
{
    __shared__ float t[32][33];
    int kt = blockIdx.y * 32, nt = blockIdx.x * 32;
    int tx = threadIdx.x, ty = threadIdx.y;   // 32 x 8
#pragma unroll
    for (int i = 0; i < 4; i++) {
        int r = ty + i * 8;
        t[r][tx] = W[(size_t)(kt + r) * N + nt + tx];
    }
    __syncthreads();
#pragma unroll
    for (int i = 0; i < 4; i++) {
        int nr = ty + i * 8;
        T[(size_t)(nt + nr) * K + kt + tx] = f2h(t[tx][nr]);
    }
}

// W[K,N] -> Wt[N,K] fp16 hi/lo
__global__ __launch_bounds__(256)
void conv_w_t3h(const float* __restrict__ W,
                ushort_t* __restrict__ Th, ushort_t* __restrict__ Tl,
                int K, int N)
{
    __shared__ float t[32][33];
    int kt = blockIdx.y * 32, nt = blockIdx.x * 32;
    int tx = threadIdx.x, ty = threadIdx.y;
#pragma unroll
    for (int i = 0; i < 4; i++) {
        int r = ty + i * 8;
        t[r][tx] = W[(size_t)(kt + r) * N + nt + tx];
    }
    __syncthreads();
#pragma unroll
    for (int i = 0; i < 4; i++) {
        int nr = ty + i * 8;
        float v = t[tx][nr];
        ushort_t h = f2h(v);
        size_t o = (size_t)(nt + nr) * K + kt + tx;
        Th[o] = h;
        Tl[o] = f2h(v - h2f(h));
    }
}

// ---------------------------------------------------------------------------
// fp16 HMMA GEMM:  C[M,N] = A[M,1024] @ Bt[N,1024]^T + bias
// NP=1: single-pass (A, B). NP=3: hi/lo 3-pass (AhBh + AlBh + AhBl).
// Block tile 128x128, BK=32, 8 warps, cp.async double buffer.
// ---------------------------------------------------------------------------
#define KC       32
#define NSTG     (DD / KC)
#define COMP_SZ  8192

template<int NP>
__global__ __launch_bounds__(256, 1)
void gemm_h(const ushort_t* __restrict__ Ah, const ushort_t* __restrict__ Al,
            const ushort_t* __restrict__ Bh, const ushort_t* __restrict__ Bl,
            const float* __restrict__ bias, float* __restrict__ C, int N)
{
    constexpr int NCOMP   = (NP == 1) ? 2 : 4;
    constexpr int BC      = (NP == 1) ? 1 : 2;     // smem comp index of B-hi
    constexpr int STAGESZ = NCOMP * COMP_SZ;

    extern __shared__ char smem[];
    const uint32_t sbase = smem_u32(smem);
    const int tid  = threadIdx.x;
    const int lane = tid & 31;
    const int wid  = tid >> 5;
    const int wm   = wid >> 1;
    const int wn   = wid & 1;
    const int mrow = wm * 32;
    const int ncol = wn * 64;
    const int bm = blockIdx.y * 128;
    const int bn = blockIdx.x * 128;

    const ushort_t* srcs[NCOMP];
    int rbase[NCOMP];
    if (NP == 1) {
        srcs[0] = Ah; srcs[1] = Bh;
        rbase[0] = bm; rbase[1] = bn;
    } else {
        srcs[0] = Ah; srcs[1] = Al; srcs[2] = Bh; srcs[3] = Bl;
        rbase[0] = bm; rbase[1] = bm; rbase[2] = bn; rbase[3] = bn;
    }

    float acc[2][8][4];
#pragma unroll
    for (int i = 0; i < 2; i++)
#pragma unroll
        for (int j = 0; j < 8; j++)
#pragma unroll
            for (int k = 0; k < 4; k++) acc[i][j][k] = 0.0f;

    const int lr[2] = {(0 * 256 + tid) >> 2, (1 * 256 + tid) >> 2};
    const int lc[2] = {(0 * 256 + tid) & 3,  (1 * 256 + tid) & 3};

    auto load_stage = [&](int c, int buf) {
        int k0 = c * KC;
        uint32_t sb = sbase + buf * STAGESZ;
#pragma unroll
        for (int comp = 0; comp < NCOMP; comp++) {
#pragma unroll
            for (int i = 0; i < 2; i++) {
                const ushort_t* g = srcs[comp]
                    + (size_t)(rbase[comp] + lr[i]) * DD + k0 + lc[i] * 8;
                cp16(sb + comp * COMP_SZ + swz64(lr[i] * 64 + lc[i] * 16), g);
            }
        }
        asm volatile("cp.async.commit_group;" ::: "memory");
    };

    load_stage(0, 0);

    for (int c = 0; c < NSTG; c++) {
        int buf = c & 1;
        if (c + 1 < NSTG) {
            load_stage(c + 1, buf ^ 1);
            asm volatile("cp.async.wait_group 1;" ::: "memory");
        } else {
            asm volatile("cp.async.wait_group 0;" ::: "memory");
        }
        __syncthreads();

        uint32_t sb = sbase + buf * STAGESZ;
#pragma unroll
        for (int ks = 0; ks < 2; ks++) {
            constexpr int AC = (NP == 1) ? 1 : 2;
            uint32_t aF[AC][2][4];
#pragma unroll
            for (int comp = 0; comp < AC; comp++)
#pragma unroll
                for (int i = 0; i < 2; i++) {
                    uint32_t row = mrow + i * 16 + (lane & 15);
                    uint32_t kb  = ks * 32 + ((lane >> 4) << 4);
                    ldsm4(aF[comp][i], sb + comp * COMP_SZ + swz64(row * 64 + kb));
                }
            uint32_t bF[AC][8][2];
#pragma unroll
            for (int comp = 0; comp < AC; comp++)
#pragma unroll
                for (int g = 0; g < 2; g++)
#pragma unroll
                    for (int h = 0; h < 2; h++) {
                        uint32_t row = ncol + g * 32 + lane;
                        uint32_t kb  = ks * 32 + h * 16;
                        uint32_t t4[4];
                        ldsm4(t4, sb + (BC + comp) * COMP_SZ + swz64(row * 64 + kb));
                        bF[comp][g * 4 + 0][h] = t4[0];
                        bF[comp][g * 4 + 1][h] = t4[1];
                        bF[comp][g * 4 + 2][h] = t4[2];
                        bF[comp][g * 4 + 3][h] = t4[3];
                    }
#pragma unroll
            for (int i = 0; i < 2; i++)
#pragma unroll
                for (int j = 0; j < 8; j++) {
                    mma_f16(acc[i][j], aF[0][i], bF[0][j]);
                    if (NP == 3) {
                        mma_f16(acc[i][j], aF[1][i], bF[0][j]);
                        mma_f16(acc[i][j], aF[0][i], bF[1][j]);
                    }
                }
        }
        __syncthreads();
    }

#pragma unroll
    for (int i = 0; i < 2; i++) {
        int row0 = bm + mrow + i * 16 + (lane >> 2);
#pragma unroll
        for (int j = 0; j < 8; j++) {
            int col = bn + ncol + j * 8 + (lane & 3) * 2;
            float2 b2 = *(const float2*)(bias + col);
            float2 o0 = {acc[i][j][0] + b2.x, acc[i][j][1] + b2.y};
            float2 o1 = {acc[i][j][2] + b2.x, acc[i][j][3] + b2.y};
            *(float2*)(C + (size_t)row0 * N + col)       = o0;
            *(float2*)(C + (size_t)(row0 + 8) * N + col) = o1;
        }
    }
}

// ---------------------------------------------------------------------------
// Tensor-core flash attention (all fp16 operands, fp32 accum/softmax).
// QK^T: 1 pass. PV: 1 pass.
// ---------------------------------------------------------------------------
#define AT_KOFF   0
#define AT_VOFF   8192
#define AT_STAGE  16384
#define AT_SMEM   (2 * AT_STAGE)   // 32KB

__global__ __launch_bounds__(256, 1)
void flash_attn_tc(const ushort_t* __restrict__ qh,
                   const ushort_t* __restrict__ kh,
                   const ushort_t* __restrict__ vh,
                   float* __restrict__ ob)
{
    extern __shared__ char smem[];
    const uint32_t sb = smem_u32(smem);
    const int tid  = threadIdx.x;
    const int lane = tid & 31;
    const int w    = tid >> 5;
    const int b    = blockIdx.z;
    const int h    = blockIdx.y;
    const int q0   = blockIdx.x * 128;

    // ---- stage Q, extract A-fragments ----
    {
        const size_t qbase = (size_t)(b * SQ + q0) * DD + h * DH;
#pragma unroll
        for (int i = 0; i < 4; i++) {
            int vi = i * 256 + tid;           // 0..1023
            int r = vi >> 3, c = vi & 7;
            cp16(sb + swz128(r * 128 + c * 16),
                 qh + qbase + (size_t)r * DD + c * 8);
        }
        asm volatile("cp.async.commit_group;" ::: "memory");
        asm volatile("cp.async.wait_group 0;" ::: "memory");
        __syncthreads();
    }
    uint32_t qf[4][4];
#pragma unroll
    for (int t = 0; t < 4; t++) {
        uint32_t row = w * 16 + (lane & 15);
        uint32_t kb  = t * 32 + ((lane >> 4) << 4);
        ldsm4(qf[t], sb + swz128(row * 128 + kb));
    }
    __syncthreads();

    // ---- state ----
    float of[8][4];
#pragma unroll
    for (int j = 0; j < 8; j++)
#pragma unroll
        for (int k = 0; k < 4; k++) of[j][k] = 0.0f;
    float m0 = -INFINITY, m1 = -INFINITY, l0 = 0.0f, l1 = 0.0f;

    const float SC  = 0.125f;
    const float L2E = 1.4426950408889634f;
    const float C2  = SC * L2E;

    const size_t kbase0 = (size_t)(b * SKV) * DD + h * DH;

    auto load_kv = [&](int tile, int buf) {
        uint32_t s = sb + buf * AT_STAGE;
        size_t gbase = kbase0 + (size_t)(tile * 64) * DD;
#pragma unroll
        for (int i = 0; i < 2; i++) {
            int vi = i * 256 + tid;           // 0..511
            int r = vi >> 3, c = vi & 7;
            uint32_t so = swz128(r * 128 + c * 16);
            size_t go = gbase + (size_t)r * DD + c * 8;
            cp16(s + AT_KOFF + so, kh + go);
            cp16(s + AT_VOFF + so, vh + go);
        }
        asm volatile("cp.async.commit_group;" ::: "memory");
    };

    load_kv(0, 0);

    for (int tile = 0; tile < SKV / 64; tile++) {
        int buf = tile & 1;
        if (tile + 1 < SKV / 64) {
            load_kv(tile + 1, buf ^ 1);
            asm volatile("cp.async.wait_group 1;" ::: "memory");
        } else {
            asm volatile("cp.async.wait_group 0;" ::: "memory");
        }
        __syncthreads();

        uint32_t s = sb + buf * AT_STAGE;

        // ---- S = Q @ K^T (fp16, 1 pass) ----
        float sf[8][4];
#pragma unroll
        for (int j = 0; j < 8; j++)
#pragma unroll
            for (int k = 0; k < 4; k++) sf[j][k] = 0.0f;

#pragma unroll
        for (int t = 0; t < 4; t++) {
            uint32_t bh[8][2];
#pragma unroll
            for (int g = 0; g < 2; g++)
#pragma unroll
                for (int hb = 0; hb < 2; hb++) {
                    uint32_t t4[4];
                    ldsm4(t4, s + AT_KOFF +
                          swz128((g * 32 + lane) * 128 + t * 32 + hb * 16));
                    bh[g * 4 + 0][hb] = t4[0];
                    bh[g * 4 + 1][hb] = t4[1];
                    bh[g * 4 + 2][hb] = t4[2];
                    bh[g * 4 + 3][hb] = t4[3];
                }
#pragma unroll
            for (int j = 0; j < 8; j++) mma_f16(sf[j], qf[t], bh[j]);
        }

        // ---- online softmax (fp32) ----
        float tm0 = -INFINITY, tm1 = -INFINITY;
#pragma unroll
        for (int j = 0; j < 8; j++) {
            tm0 = fmaxf(tm0, fmaxf(sf[j][0], sf[j][1]));
            tm1 = fmaxf(tm1, fmaxf(sf[j][2], sf[j][3]));
        }
        tm0 = fmaxf(tm0, __shfl_xor_sync(0xffffffffu, tm0, 1));
        tm0 = fmaxf(tm0, __shfl_xor_sync(0xffffffffu, tm0, 2));
        tm1 = fmaxf(tm1, __shfl_xor_sync(0xffffffffu, tm1, 1));
        tm1 = fmaxf(tm1, __shfl_xor_sync(0xffffffffu, tm1, 2));

        float mn0 = fmaxf(m0, tm0 * SC);
        float mn1 = fmaxf(m1, tm1 * SC);
        float a0 = ex2f((m0 - mn0) * L2E);
        float a1 = ex2f((m1 - mn1) * L2E);
        m0 = mn0; m1 = mn1;
        float base0 = mn0 * L2E, base1 = mn1 * L2E;

        float sum0 = 0.0f, sum1 = 0.0f;
#pragma unroll
        for (int j = 0; j < 8; j++) {
            sf[j][0] = ex2f(fmaf(sf[j][0], C2, -base0));
            sf[j][1] = ex2f(fmaf(sf[j][1], C2, -base0));
            sf[j][2] = ex2f(fmaf(sf[j][2], C2, -base1));
            sf[j][3] = ex2f(fmaf(sf[j][3], C2, -base1));
            sum0 += sf[j][0] + sf[j][1];
            sum1 += sf[j][2] + sf[j][3];
        }
        sum0 += __shfl_xor_sync(0xffffffffu, sum0, 1);
        sum0 += __shfl_xor_sync(0xffffffffu, sum0, 2);
        sum1 += __shfl_xor_sync(0xffffffffu, sum1, 1);
        sum1 += __shfl_xor_sync(0xffffffffu, sum1, 2);
        l0 = l0 * a0 + sum0;
        l1 = l1 * a1 + sum1;
#pragma unroll
        for (int j = 0; j < 8; j++) {
            of[j][0] *= a0; of[j][1] *= a0;
            of[j][2] *= a1; of[j][3] *= a1;
        }

        // ---- pack P into fp16 A fragments ----
        uint32_t pf[4][4];
#pragma unroll
        for (int t = 0; t < 4; t++) {
            pf[t][0] = packh(sf[2 * t][0],     sf[2 * t][1]);
            pf[t][1] = packh(sf[2 * t][2],     sf[2 * t][3]);
            pf[t][2] = packh(sf[2 * t + 1][0], sf[2 * t + 1][1]);
            pf[t][3] = packh(sf[2 * t + 1][2], sf[2 * t + 1][3]);
        }

        // ---- O += P @ V (fp16, 1 pass) ----
#pragma unroll
        for (int t = 0; t < 4; t++) {
#pragma unroll
            for (int g = 0; g < 4; g++) {
                uint32_t row = t * 16 + (lane & 15);
                uint32_t nb  = g * 16 + ((lane >> 4) << 3);   // elems
                uint32_t t4[4];
                ldsm4t(t4, s + AT_VOFF + swz128(row * 128 + nb * 2));
                mma_f16(of[g * 2],     pf[t], t4);
                mma_f16(of[g * 2 + 1], pf[t], t4 + 2);
            }
        }
        __syncthreads();
    }

    // ---- epilogue ----
    float inv0 = 1.0f / l0, inv1 = 1.0f / l1;
    int gr0 = q0 + w * 16 + (lane >> 2);
    int gr1 = gr0 + 8;
#pragma unroll
    for (int j = 0; j < 8; j++) {
        int col = h * DH + j * 8 + (lane & 3) * 2;
        float2 o0 = {of[j][0] * inv0, of[j][1] * inv0};
        float2 o1 = {of[j][2] * inv1, of[j][3] * inv1};
        *(float2*)(ob + (size_t)(b * SQ + gr0) * DD + col) = o0;
        *(float2*)(ob + (size_t)(b * SQ + gr1) * DD + col) = o1;
    }
}

// ---------------------------------------------------------------------------
// kernel_launch — graph-capturable, allocation-free
// Inputs: query_input, kv_input, Wq, bq, Wkv, bkv, Wo, bo
// ---------------------------------------------------------------------------
extern "C" void kernel_launch(void* const* d_in, const int* in_sizes, int n_in,
                              void* d_out, int out_size)
{
    (void)in_sizes; (void)n_in; (void)out_size;
    const float* query = (const float*)d_in[0];
    const float* kvin  = (const float*)d_in[1];
    const float* Wq    = (const float*)d_in[2];
    const float* bq    = (const float*)d_in[3];
    const float* Wkv   = (const float*)d_in[4];
    const float* bkv   = (const float*)d_in[5];
    const float* Wo    = (const float*)d_in[6];
    const float* bo    = (const float*)d_in[7];
    float* out = (float*)d_out;

    float *qbuf, *kvbuf, *attnbuf;
    ushort_t *ah, *al, *kh, *pk, *pv, *wq, *wkv, *woh, *wol;
    cudaGetSymbolAddress((void**)&qbuf,    g_q);
    cudaGetSymbolAddress((void**)&kvbuf,   g_kv);
    cudaGetSymbolAddress((void**)&attnbuf, g_attn);
    cudaGetSymbolAddress((void**)&ah,  g_ah);
    cudaGetSymbolAddress((void**)&al,  g_al);
    cudaGetSymbolAddress((void**)&kh,  g_kh);
    cudaGetSymbolAddress((void**)&pk,  g_pk);
    cudaGetSymbolAddress((void**)&pv,  g_pv);
    cudaGetSymbolAddress((void**)&wq,  g_wq);
    cudaGetSymbolAddress((void**)&wkv, g_wkv);
    cudaGetSymbolAddress((void**)&woh, g_woh);
    cudaGetSymbolAddress((void**)&wol, g_wol);

    cudaFuncSetAttribute(gemm_h<1>, cudaFuncAttributeMaxDynamicSharedMemorySize, 2 * 2 * COMP_SZ);
    cudaFuncSetAttribute(gemm_h<3>, cudaFuncAttributeMaxDynamicSharedMemorySize, 2 * 4 * COMP_SZ);
    cudaFuncSetAttribute(flash_attn_tc, cudaFuncAttributeMaxDynamicSharedMemorySize, AT_SMEM);

    const int n4 = MM * DD / 4;

    // Conversions (all fp16; Wo hi/lo for the 3-pass output projection)
    conv_h<<<(n4 + 255) / 256, 256>>>(query, ah, n4);
    conv_h<<<(n4 + 255) / 256, 256>>>(kvin, kh, n4);
    conv_w_t_h<<<dim3(DD / 32, DD / 32), dim3(32, 8)>>>(Wq, wq, DD, DD);
    conv_w_t_h<<<dim3(2 * DD / 32, DD / 32), dim3(32, 8)>>>(Wkv, wkv, DD, 2 * DD);
    conv_w_t3h<<<dim3(DD / 32, DD / 32), dim3(32, 8)>>>(Wo, woh, wol, DD, DD);

    // Projections (single-pass fp16)
    gemm_h<1><<<dim3(DD / 128, MM / 128), 256, 2 * 2 * COMP_SZ>>>(
        ah, nullptr, wq, nullptr, bq, qbuf, DD);
    gemm_h<1><<<dim3(2 * DD / 128, MM / 128), 256, 2 * 2 * COMP_SZ>>>(
        kh, nullptr, wkv, nullptr, bkv, kvbuf, 2 * DD);

    // Attention operand conversion
    conv_h<<<(n4 + 255) / 256, 256>>>(qbuf, ah, n4);
    conv_kv_h<<<(n4 + 255) / 256, 256>>>(kvbuf, pk, pv, n4);

    // Tensor-core attention
    flash_attn_tc<<<dim3(SQ / 128, HH, BB), 256, AT_SMEM>>>(ah, pk, pv, attnbuf);

    // Output projection (3-pass fp16 hi/lo)
    conv_hilo_h<<<(n4 + 255) / 256, 256>>>(attnbuf, ah, al, n4);
    gemm_h<3><<<dim3(DD / 128, MM / 128), 256, 2 * 4 * COMP_SZ>>>(
        ah, al, woh, wol, bo, out, DD);
}

// round 7
// speedup vs baseline: 6.2086x; 1.0006x over previous
#include <cuda_runtime.h>
#include <cuda_fp16.h>
#include <math.h>
#include <stdint.h>

// Problem constants
#define BB   2
#define SQ   2048
#define SKV  2048
#define DD   1024
#define HH   16
#define DH   64
#define MM   (BB*SQ)   // 4096

typedef unsigned short ushort_t;

// ---------------------------------------------------------------------------
// Scratch (no cudaMalloc allowed) — all fp16, no fp32 intermediates
// ---------------------------------------------------------------------------
__device__ ushort_t g_ah  [(size_t)MM * DD];       // projected Q fp16
__device__ ushort_t g_al  [(size_t)MM * DD];       // query-input fp16, later attn-out lo
__device__ ushort_t g_kh  [(size_t)MM * DD];       // kv-input fp16, later attn-out hi
__device__ ushort_t g_pk  [(size_t)MM * DD];       // projected K fp16
__device__ ushort_t g_pv  [(size_t)MM * DD];       // projected V fp16
__device__ ushort_t g_wq  [(size_t)DD * DD];       // Wq^T fp16
__device__ ushort_t g_wkv [(size_t)2 * DD * DD];   // Wkv^T fp16
__device__ ushort_t g_woh [(size_t)DD * DD];       // Wo^T fp16 hi
__device__ ushort_t g_wol [(size_t)DD * DD];       // Wo^T fp16 lo

// ---------------------------------------------------------------------------
// Helpers
// ---------------------------------------------------------------------------
__device__ __forceinline__ uint32_t smem_u32(const void* p) {
    uint32_t a;
    asm("{ .reg .u64 t; cvta.to.shared.u64 t, %1; cvt.u32.u64 %0, t; }"
        : "=r"(a) : "l"(p));
    return a;
}
__device__ __forceinline__ ushort_t f2h(float v) {
    __half h = __float2half_rn(v);
    return *reinterpret_cast<ushort_t*>(&h);
}
__device__ __forceinline__ float h2f(ushort_t s) {
    __half h;
    *reinterpret_cast<ushort_t*>(&h) = s;
    return __half2float(h);
}
__device__ __forceinline__ uint32_t swz64(uint32_t off) {   // 64B rows
    return off ^ ((off >> 3) & 0x30);
}
__device__ __forceinline__ uint32_t swz128(uint32_t off) {  // 128B rows
    return off ^ ((off >> 3) & 0x70);
}
__device__ __forceinline__ void ldsm4(uint32_t* r, uint32_t addr) {
    asm volatile("ldmatrix.sync.aligned.m8n8.x4.shared.b16 {%0,%1,%2,%3}, [%4];"
        : "=r"(r[0]), "=r"(r[1]), "=r"(r[2]), "=r"(r[3]) : "r"(addr));
}
__device__ __forceinline__ void ldsm4t(uint32_t* r, uint32_t addr) {
    asm volatile("ldmatrix.sync.aligned.m8n8.x4.trans.shared.b16 {%0,%1,%2,%3}, [%4];"
        : "=r"(r[0]), "=r"(r[1]), "=r"(r[2]), "=r"(r[3]) : "r"(addr));
}
__device__ __forceinline__ void mma_f16(float* d, const uint32_t* a, const uint32_t* b) {
    asm volatile(
        "mma.sync.aligned.m16n8k16.row.col.f32.f16.f16.f32 "
        "{%0,%1,%2,%3}, {%4,%5,%6,%7}, {%8,%9}, {%0,%1,%2,%3};"
        : "+f"(d[0]), "+f"(d[1]), "+f"(d[2]), "+f"(d[3])
        : "r"(a[0]), "r"(a[1]), "r"(a[2]), "r"(a[3]), "r"(b[0]), "r"(b[1]));
}
__device__ __forceinline__ void cp16(uint32_t saddr, const void* g) {
    asm volatile("cp.async.cg.shared.global [%0], [%1], 16;" :: "r"(saddr), "l"(g));
}
__device__ __forceinline__ float ex2f(float x) {
    float y;
    asm("ex2.approx.ftz.f32 %0, %1;" : "=f"(y) : "f"(x));
    return y;
}
__device__ __forceinline__ uint32_t packh(float lo, float hi) {
    uint32_t r;
    asm("cvt.rn.f16x2.f32 %0, %1, %2;" : "=r"(r) : "f"(hi), "f"(lo));
    return r;
}

// ---------------------------------------------------------------------------
// Conversion kernels (inputs + weights only)
// ---------------------------------------------------------------------------
__global__ __launch_bounds__(256)
void conv_h(const float* __restrict__ in, ushort_t* __restrict__ out, int n4)
{
    int i = blockIdx.x * 256 + threadIdx.x;
    if (i >= n4) return;
    float4 x = ((const float4*)in)[i];
    ushort4 o = {f2h(x.x), f2h(x.y), f2h(x.z), f2h(x.w)};
    ((ushort4*)out)[i] = o;
}

// W[K,N] -> Wt[N,K] fp16 single
__global__ __launch_bounds__(256)
void conv_w_t_h(const float* __restrict__ W, ushort_t* __restrict__ T,
                int K, int N)
{
    __shared__ float t[32][33];
    int kt = blockIdx.y * 32, nt = blockIdx.x * 32;
    int tx = threadIdx.x, ty = threadIdx.y;   // 32 x 8
#pragma unroll
    for (int i = 0; i < 4; i++) {
        int r = ty + i * 8;
        t[r][tx] = W[(size_t)(kt + r) * N + nt + tx];
    }
    __syncthreads();
#pragma unroll
    for (int i = 0; i < 4; i++) {
        int nr = ty + i * 8;
        T[(size_t)(nt + nr) * K + kt + tx] = f2h(t[tx][nr]);
    }
}

// W[K,N] -> Wt[N,K] fp16 hi/lo
__global__ __launch_bounds__(256)
void conv_w_t3h(const float* __restrict__ W,
                ushort_t* __restrict__ Th, ushort_t* __restrict__ Tl,
                int K, int N)
{
    __shared__ float t[32][33];
    int kt = blockIdx.y * 32, nt = blockIdx.x * 32;
    int tx = threadIdx.x, ty = threadIdx.y;
#pragma unroll
    for (int i = 0; i < 4; i++) {
        int r = ty + i * 8;
        t[r][tx] = W[(size_t)(kt + r) * N + nt + tx];
    }
    __syncthreads();
#pragma unroll
    for (int i = 0; i < 4; i++) {
        int nr = ty + i * 8;
        float v = t[tx][nr];
        ushort_t h = f2h(v);
        size_t o = (size_t)(nt + nr) * K + kt + tx;
        Th[o] = h;
        Tl[o] = f2h(v - h2f(h));
    }
}

// ---------------------------------------------------------------------------
// fp16 HMMA GEMM:  C[M,N] = A[M,1024] @ Bt[N,1024]^T + bias
// NP=1 single pass; NP=3 hi/lo 3-pass.
// EP=0: fp32 out C. EP=1: fp16 out H0. EP=2: fp16 split out (H0 if bn<DD else H1).
// ---------------------------------------------------------------------------
#define KC       32
#define NSTG     (DD / KC)
#define COMP_SZ  8192

template<int NP, int EP>
__global__ __launch_bounds__(256, 1)
void gemm_h(const ushort_t* __restrict__ Ah, const ushort_t* __restrict__ Al,
            const ushort_t* __restrict__ Bh, const ushort_t* __restrict__ Bl,
            const float* __restrict__ bias, float* __restrict__ C,
            ushort_t* __restrict__ H0, ushort_t* __restrict__ H1, int N)
{
    constexpr int NCOMP   = (NP == 1) ? 2 : 4;
    constexpr int BC      = (NP == 1) ? 1 : 2;     // smem comp index of B-hi
    constexpr int STAGESZ = NCOMP * COMP_SZ;

    extern __shared__ char smem[];
    const uint32_t sbase = smem_u32(smem);
    const int tid  = threadIdx.x;
    const int lane = tid & 31;
    const int wid  = tid >> 5;
    const int wm   = wid >> 1;
    const int wn   = wid & 1;
    const int mrow = wm * 32;
    const int ncol = wn * 64;
    const int bm = blockIdx.y * 128;
    const int bn = blockIdx.x * 128;

    const ushort_t* srcs[NCOMP];
    int rbase[NCOMP];
    if (NP == 1) {
        srcs[0] = Ah; srcs[1] = Bh;
        rbase[0] = bm; rbase[1] = bn;
    } else {
        srcs[0] = Ah; srcs[1] = Al; srcs[2] = Bh; srcs[3] = Bl;
        rbase[0] = bm; rbase[1] = bm; rbase[2] = bn; rbase[3] = bn;
    }

    float acc[2][8][4];
#pragma unroll
    for (int i = 0; i < 2; i++)
#pragma unroll
        for (int j = 0; j < 8; j++)
#pragma unroll
            for (int k = 0; k < 4; k++) acc[i][j][k] = 0.0f;

    const int lr[2] = {(0 * 256 + tid) >> 2, (1 * 256 + tid) >> 2};
    const int lc[2] = {(0 * 256 + tid) & 3,  (1 * 256 + tid) & 3};

    auto load_stage = [&](int c, int buf) {
        int k0 = c * KC;
        uint32_t sb = sbase + buf * STAGESZ;
#pragma unroll
        for (int comp = 0; comp < NCOMP; comp++) {
#pragma unroll
            for (int i = 0; i < 2; i++) {
                const ushort_t* g = srcs[comp]
                    + (size_t)(rbase[comp] + lr[i]) * DD + k0 + lc[i] * 8;
                cp16(sb + comp * COMP_SZ + swz64(lr[i] * 64 + lc[i] * 16), g);
            }
        }
        asm volatile("cp.async.commit_group;" ::: "memory");
    };

    load_stage(0, 0);

    for (int c = 0; c < NSTG; c++) {
        int buf = c & 1;
        if (c + 1 < NSTG) {
            load_stage(c + 1, buf ^ 1);
            asm volatile("cp.async.wait_group 1;" ::: "memory");
        } else {
            asm volatile("cp.async.wait_group 0;" ::: "memory");
        }
        __syncthreads();

        uint32_t sb = sbase + buf * STAGESZ;
#pragma unroll
        for (int ks = 0; ks < 2; ks++) {
            constexpr int AC = (NP == 1) ? 1 : 2;
            uint32_t aF[AC][2][4];
#pragma unroll
            for (int comp = 0; comp < AC; comp++)
#pragma unroll
                for (int i = 0; i < 2; i++) {
                    uint32_t row = mrow + i * 16 + (lane & 15);
                    uint32_t kb  = ks * 32 + ((lane >> 4) << 4);
                    ldsm4(aF[comp][i], sb + comp * COMP_SZ + swz64(row * 64 + kb));
                }
            uint32_t bF[AC][8][2];
#pragma unroll
            for (int comp = 0; comp < AC; comp++)
#pragma unroll
                for (int g = 0; g < 2; g++)
#pragma unroll
                    for (int h = 0; h < 2; h++) {
                        uint32_t row = ncol + g * 32 + lane;
                        uint32_t kb  = ks * 32 + h * 16;
                        uint32_t t4[4];
                        ldsm4(t4, sb + (BC + comp) * COMP_SZ + swz64(row * 64 + kb));
                        bF[comp][g * 4 + 0][h] = t4[0];
                        bF[comp][g * 4 + 1][h] = t4[1];
                        bF[comp][g * 4 + 2][h] = t4[2];
                        bF[comp][g * 4 + 3][h] = t4[3];
                    }
#pragma unroll
            for (int i = 0; i < 2; i++)
#pragma unroll
                for (int j = 0; j < 8; j++) {
                    mma_f16(acc[i][j], aF[0][i], bF[0][j]);
                    if (NP == 3) {
                        mma_f16(acc[i][j], aF[1][i], bF[0][j]);
                        mma_f16(acc[i][j], aF[0][i], bF[1][j]);
                    }
                }
        }
        __syncthreads();
    }

    // fused epilogue
#pragma unroll
    for (int i = 0; i < 2; i++) {
        int row0 = bm + mrow + i * 16 + (lane >> 2);
#pragma unroll
        for (int j = 0; j < 8; j++) {
            int col = bn + ncol + j * 8 + (lane & 3) * 2;
            float2 b2 = *(const float2*)(bias + col);
            float v00 = acc[i][j][0] + b2.x, v01 = acc[i][j][1] + b2.y;
            float v10 = acc[i][j][2] + b2.x, v11 = acc[i][j][3] + b2.y;
            if (EP == 0) {
                float2 o0 = {v00, v01}, o1 = {v10, v11};
                *(float2*)(C + (size_t)row0 * N + col)       = o0;
                *(float2*)(C + (size_t)(row0 + 8) * N + col) = o1;
            } else if (EP == 1) {
                ushort2 o0 = {f2h(v00), f2h(v01)};
                ushort2 o1 = {f2h(v10), f2h(v11)};
                *(ushort2*)(H0 + (size_t)row0 * N + col)       = o0;
                *(ushort2*)(H0 + (size_t)(row0 + 8) * N + col) = o1;
            } else {
                ushort_t* dst = (bn < DD) ? H0 : H1;
                int c2 = (bn < DD) ? col : col - DD;
                ushort2 o0 = {f2h(v00), f2h(v01)};
                ushort2 o1 = {f2h(v10), f2h(v11)};
                *(ushort2*)(dst + (size_t)row0 * DD + c2)       = o0;
                *(ushort2*)(dst + (size_t)(row0 + 8) * DD + c2) = o1;
            }
        }
    }
}

// ---------------------------------------------------------------------------
// Tensor-core flash attention (fp16 operands, fp32 accum/softmax).
// Output written as fp16 hi/lo directly (fused conversion).
// ---------------------------------------------------------------------------
#define AT_KOFF   0
#define AT_VOFF   8192
#define AT_STAGE  16384
#define AT_SMEM   (2 * AT_STAGE)   // 32KB

__global__ __launch_bounds__(256, 1)
void flash_attn_tc(const ushort_t* __restrict__ qh,
                   const ushort_t* __restrict__ kh,
                   const ushort_t* __restrict__ vh,
                   ushort_t* __restrict__ oh, ushort_t* __restrict__ ol)
{
    extern __shared__ char smem[];
    const uint32_t sb = smem_u32(smem);
    const int tid  = threadIdx.x;
    const int lane = tid & 31;
    const int w    = tid >> 5;
    const int b    = blockIdx.z;
    const int h    = blockIdx.y;
    const int q0   = blockIdx.x * 128;

    // ---- stage Q, extract A-fragments ----
    {
        const size_t qbase = (size_t)(b * SQ + q0) * DD + h * DH;
#pragma unroll
        for (int i = 0; i < 4; i++) {
            int vi = i * 256 + tid;           // 0..1023
            int r = vi >> 3, c = vi & 7;
            cp16(sb + swz128(r * 128 + c * 16),
                 qh + qbase + (size_t)r * DD + c * 8);
        }
        asm volatile("cp.async.commit_group;" ::: "memory");
        asm volatile("cp.async.wait_group 0;" ::: "memory");
        __syncthreads();
    }
    uint32_t qf[4][4];
#pragma unroll
    for (int t = 0; t < 4; t++) {
        uint32_t row = w * 16 + (lane & 15);
        uint32_t kb  = t * 32 + ((lane >> 4) << 4);
        ldsm4(qf[t], sb + swz128(row * 128 + kb));
    }
    __syncthreads();

    // ---- state ----
    float of[8][4];
#pragma unroll
    for (int j = 0; j < 8; j++)
#pragma unroll
        for (int k = 0; k < 4; k++) of[j][k] = 0.0f;
    float m0 = -INFINITY, m1 = -INFINITY, l0 = 0.0f, l1 = 0.0f;

    const float SC  = 0.125f;
    const float L2E = 1.4426950408889634f;
    const float C2  = SC * L2E;

    const size_t kbase0 = (size_t)(b * SKV) * DD + h * DH;

    auto load_kv = [&](int tile, int buf) {
        uint32_t s = sb + buf * AT_STAGE;
        size_t gbase = kbase0 + (size_t)(tile * 64) * DD;
#pragma unroll
        for (int i = 0; i < 2; i++) {
            int vi = i * 256 + tid;           // 0..511
            int r = vi >> 3, c = vi & 7;
            uint32_t so = swz128(r * 128 + c * 16);
            size_t go = gbase + (size_t)r * DD + c * 8;
            cp16(s + AT_KOFF + so, kh + go);
            cp16(s + AT_VOFF + so, vh + go);
        }
        asm volatile("cp.async.commit_group;" ::: "memory");
    };

    load_kv(0, 0);

    for (int tile = 0; tile < SKV / 64; tile++) {
        int buf = tile & 1;
        if (tile + 1 < SKV / 64) {
            load_kv(tile + 1, buf ^ 1);
            asm volatile("cp.async.wait_group 1;" ::: "memory");
        } else {
            asm volatile("cp.async.wait_group 0;" ::: "memory");
        }
        __syncthreads();

        uint32_t s = sb + buf * AT_STAGE;

        // ---- S = Q @ K^T ----
        float sf[8][4];
#pragma unroll
        for (int j = 0; j < 8; j++)
#pragma unroll
            for (int k = 0; k < 4; k++) sf[j][k] = 0.0f;

#pragma unroll
        for (int t = 0; t < 4; t++) {
            uint32_t bh[8][2];
#pragma unroll
            for (int g = 0; g < 2; g++)
#pragma unroll
                for (int hb = 0; hb < 2; hb++) {
                    uint32_t t4[4];
                    ldsm4(t4, s + AT_KOFF +
                          swz128((g * 32 + lane) * 128 + t * 32 + hb * 16));
                    bh[g * 4 + 0][hb] = t4[0];
                    bh[g * 4 + 1][hb] = t4[1];
                    bh[g * 4 + 2][hb] = t4[2];
                    bh[g * 4 + 3][hb] = t4[3];
                }
#pragma unroll
            for (int j = 0; j < 8; j++) mma_f16(sf[j], qf[t], bh[j]);
        }

        // ---- online softmax ----
        float tm0 = -INFINITY, tm1 = -INFINITY;
#pragma unroll
        for (int j = 0; j < 8; j++) {
            tm0 = fmaxf(tm0, fmaxf(sf[j][0], sf[j][1]));
            tm1 = fmaxf(tm1, fmaxf(sf[j][2], sf[j][3]));
        }
        tm0 = fmaxf(tm0, __shfl_xor_sync(0xffffffffu, tm0, 1));
        tm0 = fmaxf(tm0, __shfl_xor_sync(0xffffffffu, tm0, 2));
        tm1 = fmaxf(tm1, __shfl_xor_sync(0xffffffffu, tm1, 1));
        tm1 = fmaxf(tm1, __shfl_xor_sync(0xffffffffu, tm1, 2));

        float mn0 = fmaxf(m0, tm0 * SC);
        float mn1 = fmaxf(m1, tm1 * SC);
        float a0 = ex2f((m0 - mn0) * L2E);
        float a1 = ex2f((m1 - mn1) * L2E);
        m0 = mn0; m1 = mn1;
        float base0 = mn0 * L2E, base1 = mn1 * L2E;

        float sum0 = 0.0f, sum1 = 0.0f;
#pragma unroll
        for (int j = 0; j < 8; j++) {
            sf[j][0] = ex2f(fmaf(sf[j][0], C2, -base0));
            sf[j][1] = ex2f(fmaf(sf[j][1], C2, -base0));
            sf[j][2] = ex2f(fmaf(sf[j][2], C2, -base1));
            sf[j][3] = ex2f(fmaf(sf[j][3], C2, -base1));
            sum0 += sf[j][0] + sf[j][1];
            sum1 += sf[j][2] + sf[j][3];
        }
        sum0 += __shfl_xor_sync(0xffffffffu, sum0, 1);
        sum0 += __shfl_xor_sync(0xffffffffu, sum0, 2);
        sum1 += __shfl_xor_sync(0xffffffffu, sum1, 1);
        sum1 += __shfl_xor_sync(0xffffffffu, sum1, 2);
        l0 = l0 * a0 + sum0;
        l1 = l1 * a1 + sum1;
#pragma unroll
        for (int j = 0; j < 8; j++) {
            of[j][0] *= a0; of[j][1] *= a0;
            of[j][2] *= a1; of[j][3] *= a1;
        }

        // ---- pack P into fp16 A fragments ----
        uint32_t pf[4][4];
#pragma unroll
        for (int t = 0; t < 4; t++) {
            pf[t][0] = packh(sf[2 * t][0],     sf[2 * t][1]);
            pf[t][1] = packh(sf[2 * t][2],     sf[2 * t][3]);
            pf[t][2] = packh(sf[2 * t + 1][0], sf[2 * t + 1][1]);
            pf[t][3] = packh(sf[2 * t + 1][2], sf[2 * t + 1][3]);
        }

        // ---- O += P @ V ----
#pragma unroll
        for (int t = 0; t < 4; t++) {
#pragma unroll
            for (int g = 0; g < 4; g++) {
                uint32_t row = t * 16 + (lane & 15);
                uint32_t nb  = g * 16 + ((lane >> 4) << 3);   // elems
                uint32_t t4[4];
                ldsm4t(t4, s + AT_VOFF + swz128(row * 128 + nb * 2));
                mma_f16(of[g * 2],     pf[t], t4);
                mma_f16(of[g * 2 + 1], pf[t], t4 + 2);
            }
        }
        __syncthreads();
    }

    // ---- fused epilogue: write fp16 hi/lo ----
    float inv0 = 1.0f / l0, inv1 = 1.0f / l1;
    int gr0 = q0 + w * 16 + (lane >> 2);
    int gr1 = gr0 + 8;
#pragma unroll
    for (int j = 0; j < 8; j++) {
        int col = h * DH + j * 8 + (lane & 3) * 2;
        float o00 = of[j][0] * inv0, o01 = of[j][1] * inv0;
        float o10 = of[j][2] * inv1, o11 = of[j][3] * inv1;
        ushort_t h00 = f2h(o00), h01 = f2h(o01);
        ushort_t h10 = f2h(o10), h11 = f2h(o11);
        ushort2 hv0 = {h00, h01};
        ushort2 hv1 = {h10, h11};
        ushort2 lv0 = {f2h(o00 - h2f(h00)), f2h(o01 - h2f(h01))};
        ushort2 lv1 = {f2h(o10 - h2f(h10)), f2h(o11 - h2f(h11))};
        size_t off0 = (size_t)(b * SQ + gr0) * DD + col;
        size_t off1 = (size_t)(b * SQ + gr1) * DD + col;
        *(ushort2*)(oh + off0) = hv0;
        *(ushort2*)(ol + off0) = lv0;
        *(ushort2*)(oh + off1) = hv1;
        *(ushort2*)(ol + off1) = lv1;
    }
}

// ---------------------------------------------------------------------------
// kernel_launch — graph-capturable, allocation-free
// Inputs: query_input, kv_input, Wq, bq, Wkv, bkv, Wo, bo
// ---------------------------------------------------------------------------
extern "C" void kernel_launch(void* const* d_in, const int* in_sizes, int n_in,
                              void* d_out, int out_size)
{
    (void)in_sizes; (void)n_in; (void)out_size;
    const float* query = (const float*)d_in[0];
    const float* kvin  = (const float*)d_in[1];
    const float* Wq    = (const float*)d_in[2];
    const float* bq    = (const float*)d_in[3];
    const float* Wkv   = (const float*)d_in[4];
    const float* bkv   = (const float*)d_in[5];
    const float* Wo    = (const float*)d_in[6];
    const float* bo    = (const float*)d_in[7];
    float* out = (float*)d_out;

    ushort_t *ah, *al, *kh, *pk, *pv, *wq, *wkv, *woh, *wol;
    cudaGetSymbolAddress((void**)&ah,  g_ah);
    cudaGetSymbolAddress((void**)&al,  g_al);
    cudaGetSymbolAddress((void**)&kh,  g_kh);
    cudaGetSymbolAddress((void**)&pk,  g_pk);
    cudaGetSymbolAddress((void**)&pv,  g_pv);
    cudaGetSymbolAddress((void**)&wq,  g_wq);
    cudaGetSymbolAddress((void**)&wkv, g_wkv);
    cudaGetSymbolAddress((void**)&woh, g_woh);
    cudaGetSymbolAddress((void**)&wol, g_wol);

    cudaFuncSetAttribute(gemm_h<1,1>, cudaFuncAttributeMaxDynamicSharedMemorySize, 2 * 2 * COMP_SZ);
    cudaFuncSetAttribute(gemm_h<1,2>, cudaFuncAttributeMaxDynamicSharedMemorySize, 2 * 2 * COMP_SZ);
    cudaFuncSetAttribute(gemm_h<3,0>, cudaFuncAttributeMaxDynamicSharedMemorySize, 2 * 4 * COMP_SZ);
    cudaFuncSetAttribute(flash_attn_tc, cudaFuncAttributeMaxDynamicSharedMemorySize, AT_SMEM);

    const int n4 = MM * DD / 4;

    // Input/weight conversions (al = query fp16, kh = kv-input fp16)
    conv_h<<<(n4 + 255) / 256, 256>>>(query, al, n4);
    conv_h<<<(n4 + 255) / 256, 256>>>(kvin, kh, n4);
    conv_w_t_h<<<dim3(DD / 32, DD / 32), dim3(32, 8)>>>(Wq, wq, DD, DD);
    conv_w_t_h<<<dim3(2 * DD / 32, DD / 32), dim3(32, 8)>>>(Wkv, wkv, DD, 2 * DD);
    conv_w_t3h<<<dim3(DD / 32, DD / 32), dim3(32, 8)>>>(Wo, woh, wol, DD, DD);

    // Q projection -> ah (fp16, fused epilogue)
    gemm_h<1,1><<<dim3(DD / 128, MM / 128), 256, 2 * 2 * COMP_SZ>>>(
        al, nullptr, wq, nullptr, bq, nullptr, ah, nullptr, DD);
    // KV projection -> pk / pv (fp16, fused split epilogue)
    gemm_h<1,2><<<dim3(2 * DD / 128, MM / 128), 256, 2 * 2 * COMP_SZ>>>(
        kh, nullptr, wkv, nullptr, bkv, nullptr, pk, pv, 2 * DD);

    // Attention: reads ah/pk/pv, writes hi->kh, lo->al (both dead here)
    flash_attn_tc<<<dim3(SQ / 128, HH, BB), 256, AT_SMEM>>>(ah, pk, pv, kh, al);

    // Output projection (3-pass fp16 hi/lo) -> fp32 out
    gemm_h<3,0><<<dim3(DD / 128, MM / 128), 256, 2 * 4 * COMP_SZ>>>(
        kh, al, woh, wol, bo, out, nullptr, nullptr, DD);
}